// round 6
// baseline (speedup 1.0000x reference)
#include <cuda_runtime.h>
#include <math.h>

#define NB 4
#define NN 4096
#define NK 32
#define NF 128
#define EPSF 1e-8f

#define OFF_DFLAT 0
#define OFF_NUM   16384
#define OFF_SS    16388
#define OFF_PEMB  17412
#define OFF_CSUM  33796
#define OFF_RAW   34308
#define OFF_AS2   38404
#define ACC_TOTAL 38532

#define OUT_EMB   0
#define OUT_ADJ   16384
#define OUT_S     20480
#define OUT_MLOSS 544768
#define OUT_OLOSS 544769

__device__ float g_s_soft[NN * NK];
__device__ float g_w[NN];
__device__ int   g_cluster[NB * NN];
__device__ float g_acc[ACC_TOTAL];
__device__ float g_Rs[4u * NB * NN * NK];   // per-m-slice buckets, 8MB

__global__ void k_zero() {
    for (int i = blockIdx.x * blockDim.x + threadIdx.x; i < ACC_TOTAL;
         i += gridDim.x * blockDim.x)
        g_acc[i] = 0.0f;
}

__global__ void k_soft(const float* __restrict__ logits,
                       const float* __restrict__ gumbel,
                       float* __restrict__ out) {
    int n = blockIdx.x * 128 + threadIdx.x;
    float lg[32];
    const float4* lp = (const float4*)(logits + n * NK);
#pragma unroll
    for (int i = 0; i < 8; i++) {
        float4 v = lp[i];
        lg[4*i] = v.x; lg[4*i+1] = v.y; lg[4*i+2] = v.z; lg[4*i+3] = v.w;
    }
    const float t1 = 0.99995f;
    const float t2 = 0.99995f * 0.99995f;
    float x[32], mx = -3.4e38f;
#pragma unroll
    for (int k = 0; k < 32; k++) { x[k] = lg[k] / t2; mx = fmaxf(mx, x[k]); }
    float s = 0.0f;
#pragma unroll
    for (int k = 0; k < 32; k++) { x[k] = expf(x[k] - mx); s += x[k]; }
    float inv = 1.0f / s, w = 0.0f;
#pragma unroll
    for (int k = 0; k < 32; k++) { x[k] *= inv; w += x[k] * x[k]; }
    float4* sp = (float4*)(g_s_soft + n * NK);
#pragma unroll
    for (int i = 0; i < 8; i++)
        sp[i] = make_float4(x[4*i], x[4*i+1], x[4*i+2], x[4*i+3]);
    g_w[n] = w;
#pragma unroll
    for (int b = 0; b < NB; b++) {
        const float4* gp = (const float4*)(gumbel + ((size_t)(b * NN + n)) * NK);
        float best = -3.4e38f; int bi = 0;
#pragma unroll
        for (int i = 0; i < 8; i++) {
            float4 g = gp[i];
            float z;
            z = lg[4*i+0] / t1 + g.x; if (z > best) { best = z; bi = 4*i+0; }
            z = lg[4*i+1] / t1 + g.y; if (z > best) { best = z; bi = 4*i+1; }
            z = lg[4*i+2] / t1 + g.z; if (z > best) { best = z; bi = 4*i+2; }
            z = lg[4*i+3] / t1 + g.w; if (z > best) { best = z; bi = 4*i+3; }
        }
        g_cluster[b * NN + n] = bi;
        float4* op = (float4*)(out + OUT_S + ((size_t)(b * NN + n)) * NK);
#pragma unroll
        for (int i = 0; i < 8; i++) {
            float4 o;
            o.x = (4*i+0 == bi) ? 1.0f + EPSF : EPSF;
            o.y = (4*i+1 == bi) ? 1.0f + EPSF : EPSF;
            o.z = (4*i+2 == bi) ? 1.0f + EPSF : EPSF;
            o.w = (4*i+3 == bi) ? 1.0f + EPSF : EPSF;
            op[i] = o;
        }
    }
}

__global__ void k_ss() {
    __shared__ float tile[32 * 32];
    int tid = threadIdx.x;
    float acc[4] = {0, 0, 0, 0};
    int base_n = blockIdx.x * 128;
    for (int ch = 0; ch < 4; ch++) {
        __syncthreads();
        const float4* src = (const float4*)(g_s_soft + (base_n + ch * 32) * NK);
        ((float4*)tile)[tid] = src[tid];
        __syncthreads();
#pragma unroll 4
        for (int r = 0; r < 32; r++) {
#pragma unroll
            for (int p = 0; p < 4; p++) {
                int pr = tid + p * 256;
                acc[p] += tile[r * 32 + (pr >> 5)] * tile[r * 32 + (pr & 31)];
            }
        }
    }
#pragma unroll
    for (int p = 0; p < 4; p++)
        atomicAdd(&g_acc[OFF_SS + tid + p * 256], acc[p]);
}

// grid 2048 = 256 n-tiles(16 rows) x 4 m-slices(1024) x 2 batch-pairs; 128 thr.
// warp = 4 rows x 8 m-lanes (coalesced 128B/row). Buckets bank=tid (conflict-free).
__global__ void __launch_bounds__(128) k_main(const float* __restrict__ adj) {
    __shared__ float R[2 * 32 * 128];     // [bb][c*128+tid]
    __shared__ float s_mT[32 * 36];       // [feat][m_local], stride 36
    __shared__ int   c_s[2 * 32];
    int tid = threadIdx.x;
    int bp = blockIdx.x & 1, ms = (blockIdx.x >> 1) & 3, nt = blockIdx.x >> 3;
    int w = tid >> 5, r = (tid >> 3) & 3, mg = tid & 7;
    int n = nt * 16 + w * 4 + r;
    int mbase = ms * 1024;

    for (int i = tid; i < 2 * 32 * 128; i += 128) R[i] = 0.0f;

    float s_n[32];
    const float4* sp = (const float4*)(g_s_soft + n * NK);
#pragma unroll
    for (int i = 0; i < 8; i++) {
        float4 v = sp[i];
        s_n[4*i] = v.x; s_n[4*i+1] = v.y; s_n[4*i+2] = v.z; s_n[4*i+3] = v.w;
    }
    float mc[2] = {0, 0}, rs[2] = {0, 0};

    for (int ch = 0; ch < 32; ch++) {
        int m0 = mbase + ch * 32;
        __syncthreads();
#pragma unroll
        for (int j = 0; j < 2; j++) {   // stage transposed s_m (32 rows x 32 f)
            int idx = j * 128 + tid, row = idx >> 3, i4 = idx & 7;
            float4 v = ((const float4*)(g_s_soft + (m0 + row) * 32))[i4];
            float* d = s_mT + (i4 * 4) * 36 + row;
            d[0] = v.x; d[36] = v.y; d[72] = v.z; d[108] = v.w;
        }
        if (tid < 64)
            c_s[tid] = g_cluster[(bp * 2 + (tid >> 5)) * NN + m0 + (tid & 31)];
        __syncthreads();

        float G0 = 0, G1 = 0, G2 = 0, G3 = 0;
#pragma unroll
        for (int i = 0; i < 32; i++) {
            float4 v = *(const float4*)&s_mT[i * 36 + mg * 4];
            G0 += s_n[i] * v.x; G1 += s_n[i] * v.y;
            G2 += s_n[i] * v.z; G3 += s_n[i] * v.w;
        }
#pragma unroll
        for (int bb = 0; bb < 2; bb++) {
            int b = bp * 2 + bb;
            const float4* ap =
                (const float4*)(adj + ((size_t)(b * NN + n)) * NN + m0);
            float4 a = ap[mg];
            int4 c4 = *(const int4*)&c_s[bb * 32 + mg * 4];
            mc[bb] += a.x * G0 + a.y * G1 + a.z * G2 + a.w * G3;
            rs[bb] += (a.x + a.y) + (a.z + a.w);
            float* Rb = R + bb * 4096 + tid;
            Rb[c4.x << 7] += a.x;
            Rb[c4.y << 7] += a.y;
            Rb[c4.z << 7] += a.z;
            Rb[c4.w << 7] += a.w;
        }
    }
    __syncthreads();

    const unsigned F = 0xffffffffu;
#pragma unroll
    for (int bb = 0; bb < 2; bb++) {
        int b = bp * 2 + bb;
        float v = rs[bb];
        v += __shfl_xor_sync(F, v, 1);
        v += __shfl_xor_sync(F, v, 2);
        v += __shfl_xor_sync(F, v, 4);
        if (mg == 0) atomicAdd(&g_acc[OFF_DFLAT + b * NN + n], v);
        float m = mc[bb];
#pragma unroll
        for (int o = 16; o > 0; o >>= 1) m += __shfl_down_sync(F, m, o);
        if ((tid & 31) == 0) atomicAdd(&g_acc[OFF_NUM + b], m);

        float vc[32];
#pragma unroll
        for (int c = 0; c < 32; c++) {
            float x = R[bb * 4096 + (c << 7) + tid];
            x += __shfl_xor_sync(F, x, 1);
            x += __shfl_xor_sync(F, x, 2);
            x += __shfl_xor_sync(F, x, 4);
            vc[c] = x;
        }
        if (mg == 0) {
            float4* dst = (float4*)(g_Rs + ((size_t)((ms * 4 + b) * NN + n)) * 32);
#pragma unroll
            for (int i = 0; i < 8; i++)
                dst[i] = make_float4(vc[4*i], vc[4*i+1], vc[4*i+2], vc[4*i+3]);
        }
    }
}

// grid 256 = B x 64 chunks of 64 rows; 128 threads (one per f)
__global__ void k_emb(const float* __restrict__ emb) {
    __shared__ float acc[32 * 128];
    __shared__ int cl[64];
    int f = threadIdx.x;
    int b = blockIdx.x >> 6, ch = blockIdx.x & 63;
#pragma unroll
    for (int k = 0; k < 32; k++) acc[k * 128 + f] = 0.0f;
    if (f < 64) cl[f] = g_cluster[b * NN + ch * 64 + f];
    __syncthreads();
    float cs = 0.0f;
    int nbase = ch * 64;
    for (int r = 0; r < 64; r++) {
        float v = emb[((size_t)(b * NN + nbase + r)) * NF + f];
        cs += v;
        acc[cl[r] * 128 + f] += v;
    }
    __syncthreads();
#pragma unroll
    for (int k = 0; k < 32; k++)
        atomicAdd(&g_acc[OFF_PEMB + (b * 32 + k) * 128 + f], acc[k * 128 + f]);
    atomicAdd(&g_acc[OFF_CSUM + b * 128 + f], cs);
}

// grid 128 = B x 32 chunks of 128 rows; 256 thr = 8 warps
__global__ void k_oadj() {
    __shared__ float acc[8 * 32 * 32];
    __shared__ float s2[8 * 32];
    int tid = threadIdx.x, w = tid >> 5, l = tid & 31;
    int b = blockIdx.x >> 5, ch = blockIdx.x & 31;
    for (int i = tid; i < 8 * 32 * 32; i += 256) acc[i] = 0.0f;
    __syncthreads();
    float s2l = 0.0f;
    for (int r = w; r < 128; r += 8) {
        int n = ch * 128 + r;
        float as2 = EPSF * g_acc[OFF_DFLAT + b * NN + n];
#pragma unroll
        for (int s = 0; s < 4; s++)
            as2 += g_Rs[((size_t)((s * 4 + b) * NN + n)) * 32 + l];
        int c = g_cluster[b * NN + n];
        acc[(w * 32 + c) * 32 + l] += as2;
        s2l += as2;
    }
    s2[w * 32 + l] = s2l;
    __syncthreads();
#pragma unroll
    for (int p = 0; p < 4; p++) {
        int pr = tid + p * 256;
        float s = 0.0f;
#pragma unroll
        for (int ww = 0; ww < 8; ww++) s += acc[ww * 1024 + pr];
        atomicAdd(&g_acc[OFF_RAW + b * 1024 + pr], s);
    }
    if (tid < 32) {
        float s = 0.0f;
#pragma unroll
        for (int ww = 0; ww < 8; ww++) s += s2[ww * 32 + tid];
        atomicAdd(&g_acc[OFF_AS2 + b * 32 + tid], s);
    }
}

__global__ void k_fin(float* __restrict__ out) {
    __shared__ float red[256];
    __shared__ float adjb[4096];
    __shared__ float dbk[128];
    __shared__ float fro_s;
    int tid = threadIdx.x;

    float den[4] = {0, 0, 0, 0};
    for (int i = tid; i < NN; i += 256) {
        float wv = g_w[i];
#pragma unroll
        for (int b = 0; b < 4; b++) den[b] += g_acc[OFF_DFLAT + b * NN + i] * wv;
    }
    float loss = 0.0f;
    for (int b = 0; b < 4; b++) {
        red[tid] = den[b]; __syncthreads();
        for (int s = 128; s > 0; s >>= 1) {
            if (tid < s) red[tid] += red[tid + s];
            __syncthreads();
        }
        if (tid == 0) loss += g_acc[OFF_NUM + b] / red[0];
        __syncthreads();
    }
    if (tid == 0) out[OUT_MLOSS] = -0.25f * loss;

    float f2 = 0.0f;
    for (int i = tid; i < 1024; i += 256) {
        float v = g_acc[OFF_SS + i]; f2 += v * v;
    }
    red[tid] = f2; __syncthreads();
    for (int s = 128; s > 0; s >>= 1) {
        if (tid < s) red[tid] += red[tid + s];
        __syncthreads();
    }
    if (tid == 0) fro_s = sqrtf(red[0]);
    __syncthreads();
    float invf = 1.0f / fro_s;
    const float isq = 0.17677669529663687f;
    float o2 = 0.0f;
    for (int i = tid; i < 1024; i += 256) {
        float v = g_acc[OFF_SS + i] * invf;
        if ((i >> 5) == (i & 31)) v -= isq;
        o2 += v * v;
    }
    red[tid] = o2; __syncthreads();
    for (int s = 128; s > 0; s >>= 1) {
        if (tid < s) red[tid] += red[tid + s];
        __syncthreads();
    }
    if (tid == 0) out[OUT_OLOSS] = sqrtf(red[0]);

    for (int i = tid; i < 16384; i += 256) {
        int b = i >> 12, f = i & 127;
        out[OUT_EMB + i] = g_acc[OFF_PEMB + i] + EPSF * g_acc[OFF_CSUM + b * 128 + f];
    }

    for (int i = tid; i < 4096; i += 256) {
        int b = i >> 10, k = (i >> 5) & 31, l = i & 31;
        float v = (k == l) ? 0.0f
                 : g_acc[OFF_RAW + i] + EPSF * g_acc[OFF_AS2 + b * 32 + l];
        adjb[i] = v;
    }
    __syncthreads();
    if (tid < 128) {
        float s = 0.0f;
#pragma unroll
        for (int l = 0; l < 32; l++) s += adjb[tid * 32 + l];
        dbk[tid] = sqrtf(s) + EPSF;
    }
    __syncthreads();
    for (int i = tid; i < 4096; i += 256) {
        int b = i >> 10, k = (i >> 5) & 31, l = i & 31;
        out[OUT_ADJ + i] = adjb[i] / (dbk[b * 32 + k] * dbk[b * 32 + l]);
    }
}

extern "C" void kernel_launch(void* const* d_in, const int* in_sizes, int n_in,
                              void* d_out, int out_size) {
    const float* emb    = (const float*)d_in[0];
    const float* adj    = (const float*)d_in[1];
    const float* logits = (const float*)d_in[2];
    const float* gumbel = (const float*)d_in[3];
    float* out = (float*)d_out;
    k_zero<<<40, 1024>>>();
    k_soft<<<32, 128>>>(logits, gumbel, out);
    k_ss<<<32, 256>>>();
    k_main<<<2048, 128>>>(adj);
    k_emb<<<256, 128>>>(emb);
    k_oadj<<<128, 256>>>();
    k_fin<<<1, 256>>>(out);
}

// round 7
// speedup vs baseline: 1.2070x; 1.2070x over previous
#include <cuda_runtime.h>
#include <math.h>

#define NB 4
#define NN 4096
#define NK 32
#define NF 128
#define EPSF 1e-8f

#define OFF_DFLAT 0
#define OFF_NUM   16384
#define OFF_SS    16388
#define OFF_PEMB  17412
#define OFF_CSUM  33796
#define OFF_RAW   34308
#define OFF_AS2   38404
#define ACC_TOTAL 38532

#define OUT_EMB   0
#define OUT_ADJ   16384
#define OUT_S     20480
#define OUT_MLOSS 544768
#define OUT_OLOSS 544769

__device__ float g_s_soft[NN * NK];
__device__ float g_w[NN];
__device__ int   g_cluster[NB * NN];
__device__ float g_acc[ACC_TOTAL];
__device__ float g_Rs[4u * NB * NN * NK];    // per-m-slice buckets, 8MB
__device__ float g_G[(size_t)NN * NN];       // s_soft @ s_soft^T, 64MB

// softmax / argmax / s_sample; also zeroes g_acc (replaces k_zero)
__global__ void k_soft(const float* __restrict__ logits,
                       const float* __restrict__ gumbel,
                       float* __restrict__ out) {
    int gt = blockIdx.x * 128 + threadIdx.x;
    for (int i = gt; i < ACC_TOTAL; i += 32 * 128) g_acc[i] = 0.0f;
    int n = gt;
    float lg[32];
    const float4* lp = (const float4*)(logits + n * NK);
#pragma unroll
    for (int i = 0; i < 8; i++) {
        float4 v = lp[i];
        lg[4*i] = v.x; lg[4*i+1] = v.y; lg[4*i+2] = v.z; lg[4*i+3] = v.w;
    }
    const float t1 = 0.99995f;
    const float t2 = 0.99995f * 0.99995f;
    float x[32], mx = -3.4e38f;
#pragma unroll
    for (int k = 0; k < 32; k++) { x[k] = lg[k] / t2; mx = fmaxf(mx, x[k]); }
    float s = 0.0f;
#pragma unroll
    for (int k = 0; k < 32; k++) { x[k] = expf(x[k] - mx); s += x[k]; }
    float inv = 1.0f / s, w = 0.0f;
#pragma unroll
    for (int k = 0; k < 32; k++) { x[k] *= inv; w += x[k] * x[k]; }
    float4* sp = (float4*)(g_s_soft + n * NK);
#pragma unroll
    for (int i = 0; i < 8; i++)
        sp[i] = make_float4(x[4*i], x[4*i+1], x[4*i+2], x[4*i+3]);
    g_w[n] = w;
#pragma unroll
    for (int b = 0; b < NB; b++) {
        const float4* gp = (const float4*)(gumbel + ((size_t)(b * NN + n)) * NK);
        float best = -3.4e38f; int bi = 0;
#pragma unroll
        for (int i = 0; i < 8; i++) {
            float4 g = gp[i];
            float z;
            z = lg[4*i+0] / t1 + g.x; if (z > best) { best = z; bi = 4*i+0; }
            z = lg[4*i+1] / t1 + g.y; if (z > best) { best = z; bi = 4*i+1; }
            z = lg[4*i+2] / t1 + g.z; if (z > best) { best = z; bi = 4*i+2; }
            z = lg[4*i+3] / t1 + g.w; if (z > best) { best = z; bi = 4*i+3; }
        }
        g_cluster[b * NN + n] = bi;
        float4* op = (float4*)(out + OUT_S + ((size_t)(b * NN + n)) * NK);
#pragma unroll
        for (int i = 0; i < 8; i++) {
            float4 o;
            o.x = (4*i+0 == bi) ? 1.0f + EPSF : EPSF;
            o.y = (4*i+1 == bi) ? 1.0f + EPSF : EPSF;
            o.z = (4*i+2 == bi) ? 1.0f + EPSF : EPSF;
            o.w = (4*i+3 == bi) ? 1.0f + EPSF : EPSF;
            op[i] = o;
        }
    }
}

__global__ void k_ss() {
    __shared__ float tile[32 * 32];
    int tid = threadIdx.x;
    float acc[4] = {0, 0, 0, 0};
    int base_n = blockIdx.x * 128;
    for (int ch = 0; ch < 4; ch++) {
        __syncthreads();
        const float4* src = (const float4*)(g_s_soft + (base_n + ch * 32) * NK);
        ((float4*)tile)[tid] = src[tid];
        __syncthreads();
#pragma unroll 4
        for (int r = 0; r < 32; r++) {
#pragma unroll
            for (int p = 0; p < 4; p++) {
                int pr = tid + p * 256;
                acc[p] += tile[r * 32 + (pr >> 5)] * tile[r * 32 + (pr & 31)];
            }
        }
    }
#pragma unroll
    for (int p = 0; p < 4; p++)
        atomicAdd(&g_acc[OFF_SS + tid + p * 256], acc[p]);
}

// G = s_soft @ s_soft^T, 128x128 tile per CTA, 256 thr, 8x8 micro-tile
__global__ void __launch_bounds__(256) k_G() {
    __shared__ float Sa[128 * 36];      // row-major, broadcast reads
    __shared__ float SbT[32 * 132];     // [k][col], conflict-free col reads
    int tid = threadIdx.x;
    int ti = blockIdx.x >> 5, tj = blockIdx.x & 31;
    for (int i = tid; i < 1024; i += 256) {
        int row = i >> 3, q = i & 7;
        float4 va = ((const float4*)(g_s_soft + (ti * 128 + row) * 32))[q];
        *(float4*)&Sa[row * 36 + q * 4] = va;
        float4 vb = ((const float4*)(g_s_soft + (tj * 128 + row) * 32))[q];
        SbT[(q * 4 + 0) * 132 + row] = vb.x;
        SbT[(q * 4 + 1) * 132 + row] = vb.y;
        SbT[(q * 4 + 2) * 132 + row] = vb.z;
        SbT[(q * 4 + 3) * 132 + row] = vb.w;
    }
    __syncthreads();
    int ry = tid >> 4, cx = tid & 15;
    float acc[8][8];
#pragma unroll
    for (int i = 0; i < 8; i++)
#pragma unroll
        for (int j = 0; j < 8; j++) acc[i][j] = 0.0f;
#pragma unroll 4
    for (int k = 0; k < 32; k++) {
        float a[8], b[8];
#pragma unroll
        for (int i = 0; i < 8; i++) a[i] = Sa[(ry + 16 * i) * 36 + k];
#pragma unroll
        for (int j = 0; j < 8; j++) b[j] = SbT[k * 132 + cx + 16 * j];
#pragma unroll
        for (int i = 0; i < 8; i++)
#pragma unroll
            for (int j = 0; j < 8; j++) acc[i][j] += a[i] * b[j];
    }
#pragma unroll
    for (int i = 0; i < 8; i++) {
        size_t ro = (size_t)(ti * 128 + ry + 16 * i) * NN + tj * 128 + cx;
#pragma unroll
        for (int j = 0; j < 8; j++) g_G[ro + 16 * j] = acc[i][j];
    }
}

// grid 1024 = 256 n-tiles(16 rows) x 4 m-slices(1024); 128 thr; all 4 batches.
// warp = 4 rows x 8 m-lanes; no smem in inner loop except bank=tid bucket RMW.
__global__ void __launch_bounds__(128) k_main(const float* __restrict__ adj) {
    __shared__ float R[4 * 32 * 128];   // 64KB [b][c*128+tid]
    int tid = threadIdx.x;
    int nt = blockIdx.x >> 2, ms = blockIdx.x & 3;
    int w = tid >> 5, r = (tid >> 3) & 3, mg = tid & 7;
    int n = nt * 16 + w * 4 + r;
    int mbase = ms * 1024;

    for (int i = tid; i < 4 * 32 * 128; i += 128) R[i] = 0.0f;
    __syncthreads();

    float mc[4] = {0, 0, 0, 0}, rs[4] = {0, 0, 0, 0};
    const float4* Gp = (const float4*)(g_G + (size_t)n * NN + mbase);
    const float4* Ap0 = (const float4*)(adj + ((size_t)(0 * NN + n)) * NN + mbase);
    const float4* Ap1 = (const float4*)(adj + ((size_t)(1 * NN + n)) * NN + mbase);
    const float4* Ap2 = (const float4*)(adj + ((size_t)(2 * NN + n)) * NN + mbase);
    const float4* Ap3 = (const float4*)(adj + ((size_t)(3 * NN + n)) * NN + mbase);

#pragma unroll 2
    for (int it = 0; it < 32; it++) {
        int mi = it * 8 + mg;
        float4 g4 = Gp[mi];
        const float4* Ab[4] = {Ap0, Ap1, Ap2, Ap3};
#pragma unroll
        for (int b = 0; b < 4; b++) {
            float4 a = Ab[b][mi];
            int4 c4 = ((const int4*)(g_cluster + b * NN + mbase))[mi];
            mc[b] += a.x * g4.x + a.y * g4.y + a.z * g4.z + a.w * g4.w;
            rs[b] += (a.x + a.y) + (a.z + a.w);
            float* Rb = R + b * 4096 + tid;
            Rb[c4.x << 7] += a.x;
            Rb[c4.y << 7] += a.y;
            Rb[c4.z << 7] += a.z;
            Rb[c4.w << 7] += a.w;
        }
    }

    const unsigned F = 0xffffffffu;
#pragma unroll
    for (int b = 0; b < 4; b++) {
        float v = rs[b];
        v += __shfl_xor_sync(F, v, 1);
        v += __shfl_xor_sync(F, v, 2);
        v += __shfl_xor_sync(F, v, 4);
        if (mg == 0) atomicAdd(&g_acc[OFF_DFLAT + b * NN + n], v);
        float m = mc[b];
#pragma unroll
        for (int o = 16; o > 0; o >>= 1) m += __shfl_down_sync(F, m, o);
        if ((tid & 31) == 0) atomicAdd(&g_acc[OFF_NUM + b], m);

        float vc[32];
#pragma unroll
        for (int c = 0; c < 32; c++) {
            float x = R[b * 4096 + (c << 7) + tid];
            x += __shfl_xor_sync(F, x, 1);
            x += __shfl_xor_sync(F, x, 2);
            x += __shfl_xor_sync(F, x, 4);
            vc[c] = x;
        }
        if (mg == 0) {
            float4* dst = (float4*)(g_Rs + ((size_t)((ms * 4 + b) * NN + n)) * 32);
#pragma unroll
            for (int i = 0; i < 8; i++)
                dst[i] = make_float4(vc[4*i], vc[4*i+1], vc[4*i+2], vc[4*i+3]);
        }
    }
}

// grid 256 = B x 64 chunks of 64 rows; 128 threads (one per f)
__global__ void k_emb(const float* __restrict__ emb) {
    __shared__ float acc[32 * 128];
    __shared__ int cl[64];
    int f = threadIdx.x;
    int b = blockIdx.x >> 6, ch = blockIdx.x & 63;
#pragma unroll
    for (int k = 0; k < 32; k++) acc[k * 128 + f] = 0.0f;
    if (f < 64) cl[f] = g_cluster[b * NN + ch * 64 + f];
    __syncthreads();
    float cs = 0.0f;
    int nbase = ch * 64;
    for (int r = 0; r < 64; r++) {
        float v = emb[((size_t)(b * NN + nbase + r)) * NF + f];
        cs += v;
        acc[cl[r] * 128 + f] += v;
    }
    __syncthreads();
#pragma unroll
    for (int k = 0; k < 32; k++)
        atomicAdd(&g_acc[OFF_PEMB + (b * 32 + k) * 128 + f], acc[k * 128 + f]);
    atomicAdd(&g_acc[OFF_CSUM + b * 128 + f], cs);
}

// grid 128 = B x 32 chunks of 128 rows; 256 thr = 8 warps
__global__ void k_oadj() {
    __shared__ float acc[8 * 32 * 32];
    __shared__ float s2[8 * 32];
    int tid = threadIdx.x, w = tid >> 5, l = tid & 31;
    int b = blockIdx.x >> 5, ch = blockIdx.x & 31;
    for (int i = tid; i < 8 * 32 * 32; i += 256) acc[i] = 0.0f;
    __syncthreads();
    float s2l = 0.0f;
    for (int r = w; r < 128; r += 8) {
        int n = ch * 128 + r;
        float as2 = EPSF * g_acc[OFF_DFLAT + b * NN + n];
#pragma unroll
        for (int s = 0; s < 4; s++)
            as2 += g_Rs[((size_t)((s * 4 + b) * NN + n)) * 32 + l];
        int c = g_cluster[b * NN + n];
        acc[(w * 32 + c) * 32 + l] += as2;
        s2l += as2;
    }
    s2[w * 32 + l] = s2l;
    __syncthreads();
#pragma unroll
    for (int p = 0; p < 4; p++) {
        int pr = tid + p * 256;
        float s = 0.0f;
#pragma unroll
        for (int ww = 0; ww < 8; ww++) s += acc[ww * 1024 + pr];
        atomicAdd(&g_acc[OFF_RAW + b * 1024 + pr], s);
    }
    if (tid < 32) {
        float s = 0.0f;
#pragma unroll
        for (int ww = 0; ww < 8; ww++) s += s2[ww * 32 + tid];
        atomicAdd(&g_acc[OFF_AS2 + b * 32 + tid], s);
    }
}

__global__ void k_fin(float* __restrict__ out) {
    __shared__ float red[256];
    __shared__ float adjb[4096];
    __shared__ float dbk[128];
    __shared__ float fro_s;
    int tid = threadIdx.x;

    float den[4] = {0, 0, 0, 0};
    for (int i = tid; i < NN; i += 256) {
        float wv = g_w[i];
#pragma unroll
        for (int b = 0; b < 4; b++) den[b] += g_acc[OFF_DFLAT + b * NN + i] * wv;
    }
    float loss = 0.0f;
    for (int b = 0; b < 4; b++) {
        red[tid] = den[b]; __syncthreads();
        for (int s = 128; s > 0; s >>= 1) {
            if (tid < s) red[tid] += red[tid + s];
            __syncthreads();
        }
        if (tid == 0) loss += g_acc[OFF_NUM + b] / red[0];
        __syncthreads();
    }
    if (tid == 0) out[OUT_MLOSS] = -0.25f * loss;

    float f2 = 0.0f;
    for (int i = tid; i < 1024; i += 256) {
        float v = g_acc[OFF_SS + i]; f2 += v * v;
    }
    red[tid] = f2; __syncthreads();
    for (int s = 128; s > 0; s >>= 1) {
        if (tid < s) red[tid] += red[tid + s];
        __syncthreads();
    }
    if (tid == 0) fro_s = sqrtf(red[0]);
    __syncthreads();
    float invf = 1.0f / fro_s;
    const float isq = 0.17677669529663687f;
    float o2 = 0.0f;
    for (int i = tid; i < 1024; i += 256) {
        float v = g_acc[OFF_SS + i] * invf;
        if ((i >> 5) == (i & 31)) v -= isq;
        o2 += v * v;
    }
    red[tid] = o2; __syncthreads();
    for (int s = 128; s > 0; s >>= 1) {
        if (tid < s) red[tid] += red[tid + s];
        __syncthreads();
    }
    if (tid == 0) out[OUT_OLOSS] = sqrtf(red[0]);

    for (int i = tid; i < 16384; i += 256) {
        int b = i >> 12, f = i & 127;
        out[OUT_EMB + i] = g_acc[OFF_PEMB + i] + EPSF * g_acc[OFF_CSUM + b * 128 + f];
    }

    for (int i = tid; i < 4096; i += 256) {
        int b = i >> 10, k = (i >> 5) & 31, l = i & 31;
        float v = (k == l) ? 0.0f
                 : g_acc[OFF_RAW + i] + EPSF * g_acc[OFF_AS2 + b * 32 + l];
        adjb[i] = v;
    }
    __syncthreads();
    if (tid < 128) {
        float s = 0.0f;
#pragma unroll
        for (int l = 0; l < 32; l++) s += adjb[tid * 32 + l];
        dbk[tid] = sqrtf(s) + EPSF;
    }
    __syncthreads();
    for (int i = tid; i < 4096; i += 256) {
        int b = i >> 10, k = (i >> 5) & 31, l = i & 31;
        out[OUT_ADJ + i] = adjb[i] / (dbk[b * 32 + k] * dbk[b * 32 + l]);
    }
}

extern "C" void kernel_launch(void* const* d_in, const int* in_sizes, int n_in,
                              void* d_out, int out_size) {
    const float* emb    = (const float*)d_in[0];
    const float* adj    = (const float*)d_in[1];
    const float* logits = (const float*)d_in[2];
    const float* gumbel = (const float*)d_in[3];
    float* out = (float*)d_out;
    k_soft<<<32, 128>>>(logits, gumbel, out);
    k_ss<<<32, 256>>>();
    k_G<<<1024, 256>>>();
    k_main<<<1024, 128>>>(adj);
    k_emb<<<256, 128>>>(emb);
    k_oadj<<<128, 256>>>();
    k_fin<<<1, 256>>>(out);
}

// round 8
// speedup vs baseline: 1.4054x; 1.1644x over previous
#include <cuda_runtime.h>
#include <math.h>

#define NB 4
#define NN 4096
#define NK 32
#define NF 128
#define EPSF 1e-8f

#define OFF_DFLAT 0
#define OFF_NUM   16384
#define OFF_SS    16388
#define OFF_PEMB  17412
#define OFF_CSUM  33796
#define OFF_RAW   34308
#define OFF_AS2   38404
#define ACC_TOTAL 38532

#define OUT_EMB   0
#define OUT_ADJ   16384
#define OUT_S     20480
#define OUT_MLOSS 544768
#define OUT_OLOSS 544769

__device__ float g_s_soft[NN * NK];
__device__ float g_w[NN];
__device__ int   g_cluster[NB * NN];
__device__ float g_acc[ACC_TOTAL];
__device__ float g_Rs[4u * NB * NN * NK];    // per-m-slice buckets, 8MB
__device__ float g_G[(size_t)NN * NN];       // s_soft @ s_soft^T, 64MB

__global__ void k_soft(const float* __restrict__ logits,
                       const float* __restrict__ gumbel,
                       float* __restrict__ out) {
    int gt = blockIdx.x * 128 + threadIdx.x;
    for (int i = gt; i < ACC_TOTAL; i += 32 * 128) g_acc[i] = 0.0f;
    int n = gt;
    float lg[32];
    const float4* lp = (const float4*)(logits + n * NK);
#pragma unroll
    for (int i = 0; i < 8; i++) {
        float4 v = lp[i];
        lg[4*i] = v.x; lg[4*i+1] = v.y; lg[4*i+2] = v.z; lg[4*i+3] = v.w;
    }
    const float t1 = 0.99995f;
    const float t2 = 0.99995f * 0.99995f;
    float x[32], mx = -3.4e38f;
#pragma unroll
    for (int k = 0; k < 32; k++) { x[k] = lg[k] / t2; mx = fmaxf(mx, x[k]); }
    float s = 0.0f;
#pragma unroll
    for (int k = 0; k < 32; k++) { x[k] = expf(x[k] - mx); s += x[k]; }
    float inv = 1.0f / s, w = 0.0f;
#pragma unroll
    for (int k = 0; k < 32; k++) { x[k] *= inv; w += x[k] * x[k]; }
    float4* sp = (float4*)(g_s_soft + n * NK);
#pragma unroll
    for (int i = 0; i < 8; i++)
        sp[i] = make_float4(x[4*i], x[4*i+1], x[4*i+2], x[4*i+3]);
    g_w[n] = w;
#pragma unroll
    for (int b = 0; b < NB; b++) {
        const float4* gp = (const float4*)(gumbel + ((size_t)(b * NN + n)) * NK);
        float best = -3.4e38f; int bi = 0;
#pragma unroll
        for (int i = 0; i < 8; i++) {
            float4 g = gp[i];
            float z;
            z = lg[4*i+0] / t1 + g.x; if (z > best) { best = z; bi = 4*i+0; }
            z = lg[4*i+1] / t1 + g.y; if (z > best) { best = z; bi = 4*i+1; }
            z = lg[4*i+2] / t1 + g.z; if (z > best) { best = z; bi = 4*i+2; }
            z = lg[4*i+3] / t1 + g.w; if (z > best) { best = z; bi = 4*i+3; }
        }
        g_cluster[b * NN + n] = bi;
        float4* op = (float4*)(out + OUT_S + ((size_t)(b * NN + n)) * NK);
#pragma unroll
        for (int i = 0; i < 8; i++) {
            float4 o;
            o.x = (4*i+0 == bi) ? 1.0f + EPSF : EPSF;
            o.y = (4*i+1 == bi) ? 1.0f + EPSF : EPSF;
            o.z = (4*i+2 == bi) ? 1.0f + EPSF : EPSF;
            o.w = (4*i+3 == bi) ? 1.0f + EPSF : EPSF;
            op[i] = o;
        }
    }
}

__global__ void k_ss() {
    __shared__ float tile[32 * 32];
    int tid = threadIdx.x;
    float acc[4] = {0, 0, 0, 0};
    int base_n = blockIdx.x * 128;
    for (int ch = 0; ch < 4; ch++) {
        __syncthreads();
        const float4* src = (const float4*)(g_s_soft + (base_n + ch * 32) * NK);
        ((float4*)tile)[tid] = src[tid];
        __syncthreads();
#pragma unroll 4
        for (int r = 0; r < 32; r++) {
#pragma unroll
            for (int p = 0; p < 4; p++) {
                int pr = tid + p * 256;
                acc[p] += tile[r * 32 + (pr >> 5)] * tile[r * 32 + (pr & 31)];
            }
        }
    }
#pragma unroll
    for (int p = 0; p < 4; p++)
        atomicAdd(&g_acc[OFF_SS + tid + p * 256], acc[p]);
}

// G = s_soft @ s_soft^T, 128x128 tile per CTA, 256 thr, 8x8 via packed f32x2
__global__ void __launch_bounds__(256) k_G() {
    __shared__ float Sa[128 * 36];
    __shared__ float SbT[32 * 132];
    int tid = threadIdx.x;
    int ti = blockIdx.x >> 5, tj = blockIdx.x & 31;
    for (int i = tid; i < 1024; i += 256) {
        int row = i >> 3, q = i & 7;
        float4 va = ((const float4*)(g_s_soft + (ti * 128 + row) * 32))[q];
        *(float4*)&Sa[row * 36 + q * 4] = va;
        float4 vb = ((const float4*)(g_s_soft + (tj * 128 + row) * 32))[q];
        SbT[(q * 4 + 0) * 132 + row] = vb.x;
        SbT[(q * 4 + 1) * 132 + row] = vb.y;
        SbT[(q * 4 + 2) * 132 + row] = vb.z;
        SbT[(q * 4 + 3) * 132 + row] = vb.w;
    }
    __syncthreads();
    int ry = tid >> 4, cx = tid & 15;
    unsigned long long acc2[8][4];
#pragma unroll
    for (int i = 0; i < 8; i++)
#pragma unroll
        for (int j = 0; j < 4; j++) acc2[i][j] = 0ull;
#pragma unroll 4
    for (int k = 0; k < 32; k++) {
        unsigned long long a2[8], b2[4];
#pragma unroll
        for (int i = 0; i < 8; i++) {
            float a = Sa[(ry + 16 * i) * 36 + k];
            asm("mov.b64 %0, {%1, %1};" : "=l"(a2[i]) : "f"(a));
        }
#pragma unroll
        for (int j = 0; j < 4; j++) {
            float blo = SbT[k * 132 + cx + 32 * j];
            float bhi = SbT[k * 132 + cx + 32 * j + 16];
            asm("mov.b64 %0, {%1, %2};" : "=l"(b2[j]) : "f"(blo), "f"(bhi));
        }
#pragma unroll
        for (int i = 0; i < 8; i++)
#pragma unroll
            for (int j = 0; j < 4; j++)
                asm("fma.rn.f32x2 %0, %1, %2, %0;"
                    : "+l"(acc2[i][j]) : "l"(a2[i]), "l"(b2[j]));
    }
#pragma unroll
    for (int i = 0; i < 8; i++) {
        size_t ro = (size_t)(ti * 128 + ry + 16 * i) * NN + tj * 128 + cx;
#pragma unroll
        for (int j = 0; j < 4; j++) {
            float lo, hi;
            asm("mov.b64 {%0, %1}, %2;" : "=f"(lo), "=f"(hi) : "l"(acc2[i][j]));
            g_G[ro + 32 * j] = lo;
            g_G[ro + 32 * j + 16] = hi;
        }
    }
}

// grid 2048 = 256 n-tiles(16 rows) x 4 m-slices x 2 batch-pairs (bp = low bit);
// 128 thr, warp = 4 rows x 8 m-lanes; buckets R[bb][c*128+tid] bank=tid.
__global__ void __launch_bounds__(128, 6) k_main(const float* __restrict__ adj) {
    __shared__ float R[2 * 32 * 128];   // 32KB
    int tid = threadIdx.x;
    int bp = blockIdx.x & 1, ms = (blockIdx.x >> 1) & 3, nt = blockIdx.x >> 3;
    int w = tid >> 5, r = (tid >> 3) & 3, mg = tid & 7;
    int n = nt * 16 + w * 4 + r;
    int mbase = ms * 1024;

    for (int i = tid; i < 2 * 32 * 128; i += 128) R[i] = 0.0f;
    __syncthreads();

    float mc[2] = {0, 0}, rs[2] = {0, 0};
    const float4* Gp = (const float4*)(g_G + (size_t)n * NN + mbase);
    const float4* Ap0 =
        (const float4*)(adj + ((size_t)((bp * 2 + 0) * NN + n)) * NN + mbase);
    const float4* Ap1 =
        (const float4*)(adj + ((size_t)((bp * 2 + 1) * NN + n)) * NN + mbase);
    const int4* Cp0 = (const int4*)(g_cluster + (bp * 2 + 0) * NN + mbase);
    const int4* Cp1 = (const int4*)(g_cluster + (bp * 2 + 1) * NN + mbase);

#pragma unroll 4
    for (int it = 0; it < 32; it++) {
        int mi = it * 8 + mg;
        float4 g4 = Gp[mi];
        float4 a0 = Ap0[mi];
        float4 a1 = Ap1[mi];
        int4 c0 = Cp0[mi];
        int4 c1 = Cp1[mi];
        mc[0] += a0.x * g4.x + a0.y * g4.y + a0.z * g4.z + a0.w * g4.w;
        rs[0] += (a0.x + a0.y) + (a0.z + a0.w);
        mc[1] += a1.x * g4.x + a1.y * g4.y + a1.z * g4.z + a1.w * g4.w;
        rs[1] += (a1.x + a1.y) + (a1.z + a1.w);
        float* R0 = R + tid;
        R0[c0.x << 7] += a0.x;
        R0[c0.y << 7] += a0.y;
        R0[c0.z << 7] += a0.z;
        R0[c0.w << 7] += a0.w;
        float* R1 = R + 4096 + tid;
        R1[c1.x << 7] += a1.x;
        R1[c1.y << 7] += a1.y;
        R1[c1.z << 7] += a1.z;
        R1[c1.w << 7] += a1.w;
    }

    const unsigned F = 0xffffffffu;
#pragma unroll
    for (int bb = 0; bb < 2; bb++) {
        int b = bp * 2 + bb;
        float v = rs[bb];
        v += __shfl_xor_sync(F, v, 1);
        v += __shfl_xor_sync(F, v, 2);
        v += __shfl_xor_sync(F, v, 4);
        if (mg == 0) atomicAdd(&g_acc[OFF_DFLAT + b * NN + n], v);
        float m = mc[bb];
#pragma unroll
        for (int o = 16; o > 0; o >>= 1) m += __shfl_down_sync(F, m, o);
        if ((tid & 31) == 0) atomicAdd(&g_acc[OFF_NUM + b], m);

        float vc[32];
#pragma unroll
        for (int c = 0; c < 32; c++) {
            float x = R[bb * 4096 + (c << 7) + tid];
            x += __shfl_xor_sync(F, x, 1);
            x += __shfl_xor_sync(F, x, 2);
            x += __shfl_xor_sync(F, x, 4);
            vc[c] = x;
        }
        if (mg == 0) {
            float4* dst = (float4*)(g_Rs + ((size_t)((ms * 4 + b) * NN + n)) * 32);
#pragma unroll
            for (int i = 0; i < 8; i++)
                dst[i] = make_float4(vc[4*i], vc[4*i+1], vc[4*i+2], vc[4*i+3]);
        }
    }
}

// grid 256 = B x 64 chunks of 64 rows; 128 threads (one per f)
__global__ void k_emb(const float* __restrict__ emb) {
    __shared__ float acc[32 * 128];
    __shared__ int cl[64];
    int f = threadIdx.x;
    int b = blockIdx.x >> 6, ch = blockIdx.x & 63;
#pragma unroll
    for (int k = 0; k < 32; k++) acc[k * 128 + f] = 0.0f;
    if (f < 64) cl[f] = g_cluster[b * NN + ch * 64 + f];
    __syncthreads();
    float cs = 0.0f;
    int nbase = ch * 64;
    for (int r = 0; r < 64; r++) {
        float v = emb[((size_t)(b * NN + nbase + r)) * NF + f];
        cs += v;
        acc[cl[r] * 128 + f] += v;
    }
    __syncthreads();
#pragma unroll
    for (int k = 0; k < 32; k++)
        atomicAdd(&g_acc[OFF_PEMB + (b * 32 + k) * 128 + f], acc[k * 128 + f]);
    atomicAdd(&g_acc[OFF_CSUM + b * 128 + f], cs);
}

// grid 128 = B x 32 chunks of 128 rows; 256 thr = 8 warps
__global__ void k_oadj() {
    __shared__ float acc[8 * 32 * 32];
    __shared__ float s2[8 * 32];
    int tid = threadIdx.x, w = tid >> 5, l = tid & 31;
    int b = blockIdx.x >> 5, ch = blockIdx.x & 31;
    for (int i = tid; i < 8 * 32 * 32; i += 256) acc[i] = 0.0f;
    __syncthreads();
    float s2l = 0.0f;
    for (int r = w; r < 128; r += 8) {
        int n = ch * 128 + r;
        float as2 = EPSF * g_acc[OFF_DFLAT + b * NN + n];
#pragma unroll
        for (int s = 0; s < 4; s++)
            as2 += g_Rs[((size_t)((s * 4 + b) * NN + n)) * 32 + l];
        int c = g_cluster[b * NN + n];
        acc[(w * 32 + c) * 32 + l] += as2;
        s2l += as2;
    }
    s2[w * 32 + l] = s2l;
    __syncthreads();
#pragma unroll
    for (int p = 0; p < 4; p++) {
        int pr = tid + p * 256;
        float s = 0.0f;
#pragma unroll
        for (int ww = 0; ww < 8; ww++) s += acc[ww * 1024 + pr];
        atomicAdd(&g_acc[OFF_RAW + b * 1024 + pr], s);
    }
    if (tid < 32) {
        float s = 0.0f;
#pragma unroll
        for (int ww = 0; ww < 8; ww++) s += s2[ww * 32 + tid];
        atomicAdd(&g_acc[OFF_AS2 + b * 32 + tid], s);
    }
}

__global__ void k_fin(float* __restrict__ out) {
    __shared__ float red[256];
    __shared__ float adjb[4096];
    __shared__ float dbk[128];
    __shared__ float fro_s;
    int tid = threadIdx.x;

    float den[4] = {0, 0, 0, 0};
    for (int i = tid; i < NN; i += 256) {
        float wv = g_w[i];
#pragma unroll
        for (int b = 0; b < 4; b++) den[b] += g_acc[OFF_DFLAT + b * NN + i] * wv;
    }
    float loss = 0.0f;
    for (int b = 0; b < 4; b++) {
        red[tid] = den[b]; __syncthreads();
        for (int s = 128; s > 0; s >>= 1) {
            if (tid < s) red[tid] += red[tid + s];
            __syncthreads();
        }
        if (tid == 0) loss += g_acc[OFF_NUM + b] / red[0];
        __syncthreads();
    }
    if (tid == 0) out[OUT_MLOSS] = -0.25f * loss;

    float f2 = 0.0f;
    for (int i = tid; i < 1024; i += 256) {
        float v = g_acc[OFF_SS + i]; f2 += v * v;
    }
    red[tid] = f2; __syncthreads();
    for (int s = 128; s > 0; s >>= 1) {
        if (tid < s) red[tid] += red[tid + s];
        __syncthreads();
    }
    if (tid == 0) fro_s = sqrtf(red[0]);
    __syncthreads();
    float invf = 1.0f / fro_s;
    const float isq = 0.17677669529663687f;
    float o2 = 0.0f;
    for (int i = tid; i < 1024; i += 256) {
        float v = g_acc[OFF_SS + i] * invf;
        if ((i >> 5) == (i & 31)) v -= isq;
        o2 += v * v;
    }
    red[tid] = o2; __syncthreads();
    for (int s = 128; s > 0; s >>= 1) {
        if (tid < s) red[tid] += red[tid + s];
        __syncthreads();
    }
    if (tid == 0) out[OUT_OLOSS] = sqrtf(red[0]);

    for (int i = tid; i < 16384; i += 256) {
        int b = i >> 12, f = i & 127;
        out[OUT_EMB + i] = g_acc[OFF_PEMB + i] + EPSF * g_acc[OFF_CSUM + b * 128 + f];
    }

    for (int i = tid; i < 4096; i += 256) {
        int b = i >> 10, k = (i >> 5) & 31, l = i & 31;
        float v = (k == l) ? 0.0f
                 : g_acc[OFF_RAW + i] + EPSF * g_acc[OFF_AS2 + b * 32 + l];
        adjb[i] = v;
    }
    __syncthreads();
    if (tid < 128) {
        float s = 0.0f;
#pragma unroll
        for (int l = 0; l < 32; l++) s += adjb[tid * 32 + l];
        dbk[tid] = sqrtf(s) + EPSF;
    }
    __syncthreads();
    for (int i = tid; i < 4096; i += 256) {
        int b = i >> 10, k = (i >> 5) & 31, l = i & 31;
        out[OUT_ADJ + i] = adjb[i] / (dbk[b * 32 + k] * dbk[b * 32 + l]);
    }
}

extern "C" void kernel_launch(void* const* d_in, const int* in_sizes, int n_in,
                              void* d_out, int out_size) {
    const float* emb    = (const float*)d_in[0];
    const float* adj    = (const float*)d_in[1];
    const float* logits = (const float*)d_in[2];
    const float* gumbel = (const float*)d_in[3];
    float* out = (float*)d_out;
    k_soft<<<32, 128>>>(logits, gumbel, out);
    k_ss<<<32, 256>>>();
    k_G<<<1024, 256>>>();
    k_main<<<2048, 128>>>(adj);
    k_emb<<<256, 128>>>(emb);
    k_oadj<<<128, 256>>>();
    k_fin<<<1, 256>>>(out);
}

// round 10
// speedup vs baseline: 1.5329x; 1.0907x over previous
#include <cuda_runtime.h>
#include <cuda_bf16.h>
#include <math.h>

#define NB 4
#define NN 4096
#define NK 32
#define NF 128
#define EPSF 1e-8f

#define OFF_DFLAT 0
#define OFF_NUM   16384
#define OFF_SS    16388
#define OFF_PEMB  17412
#define OFF_CSUM  33796
#define OFF_RAW   34308
#define OFF_AS2   38404
#define ACC_TOTAL 38532

#define OUT_EMB   0
#define OUT_ADJ   16384
#define OUT_S     20480
#define OUT_MLOSS 544768
#define OUT_OLOSS 544769

__device__ float g_s_soft[NN * NK];
__device__ float g_w[NN];
__device__ int   g_cluster[NB * NN];
__device__ float g_acc[ACC_TOTAL];
__device__ float g_Rs[4u * NB * NN * NK];          // per-m-slice buckets, 8MB
__device__ __nv_bfloat16 g_Gh[(size_t)NN * NN];    // G in bf16, 32MB

__global__ void k_soft(const float* __restrict__ logits,
                       const float* __restrict__ gumbel,
                       float* __restrict__ out) {
    int n = blockIdx.x * 32 + threadIdx.x;
    for (int i = n; i < ACC_TOTAL; i += 4096) g_acc[i] = 0.0f;
    float lg[32];
    const float4* lp = (const float4*)(logits + n * NK);
#pragma unroll
    for (int i = 0; i < 8; i++) {
        float4 v = lp[i];
        lg[4*i] = v.x; lg[4*i+1] = v.y; lg[4*i+2] = v.z; lg[4*i+3] = v.w;
    }
    const float t1 = 0.99995f;
    const float t2 = 0.99995f * 0.99995f;
    float x[32], mx = -3.4e38f;
#pragma unroll
    for (int k = 0; k < 32; k++) { x[k] = lg[k] / t2; mx = fmaxf(mx, x[k]); }
    float s = 0.0f;
#pragma unroll
    for (int k = 0; k < 32; k++) { x[k] = expf(x[k] - mx); s += x[k]; }
    float inv = 1.0f / s, w = 0.0f;
#pragma unroll
    for (int k = 0; k < 32; k++) { x[k] *= inv; w += x[k] * x[k]; }
    float4* sp = (float4*)(g_s_soft + n * NK);
#pragma unroll
    for (int i = 0; i < 8; i++)
        sp[i] = make_float4(x[4*i], x[4*i+1], x[4*i+2], x[4*i+3]);
    g_w[n] = w;
#pragma unroll
    for (int b = 0; b < NB; b++) {
        const float4* gp = (const float4*)(gumbel + ((size_t)(b * NN + n)) * NK);
        float best = -3.4e38f; int bi = 0;
#pragma unroll
        for (int i = 0; i < 8; i++) {
            float4 g = gp[i];
            float z;
            z = lg[4*i+0] / t1 + g.x; if (z > best) { best = z; bi = 4*i+0; }
            z = lg[4*i+1] / t1 + g.y; if (z > best) { best = z; bi = 4*i+1; }
            z = lg[4*i+2] / t1 + g.z; if (z > best) { best = z; bi = 4*i+2; }
            z = lg[4*i+3] / t1 + g.w; if (z > best) { best = z; bi = 4*i+3; }
        }
        g_cluster[b * NN + n] = bi;
        float4* op = (float4*)(out + OUT_S + ((size_t)(b * NN + n)) * NK);
#pragma unroll
        for (int i = 0; i < 8; i++) {
            float4 o;
            o.x = (4*i+0 == bi) ? 1.0f + EPSF : EPSF;
            o.y = (4*i+1 == bi) ? 1.0f + EPSF : EPSF;
            o.z = (4*i+2 == bi) ? 1.0f + EPSF : EPSF;
            o.w = (4*i+3 == bi) ? 1.0f + EPSF : EPSF;
            op[i] = o;
        }
    }
}

__global__ void k_ss() {
    __shared__ float tile[32 * 32];
    int tid = threadIdx.x;
    float acc[4] = {0, 0, 0, 0};
    int base_n = blockIdx.x * 128;
    for (int ch = 0; ch < 4; ch++) {
        __syncthreads();
        const float4* src = (const float4*)(g_s_soft + (base_n + ch * 32) * NK);
        ((float4*)tile)[tid] = src[tid];
        __syncthreads();
#pragma unroll 4
        for (int r = 0; r < 32; r++) {
#pragma unroll
            for (int p = 0; p < 4; p++) {
                int pr = tid + p * 256;
                acc[p] += tile[r * 32 + (pr >> 5)] * tile[r * 32 + (pr & 31)];
            }
        }
    }
#pragma unroll
    for (int p = 0; p < 4; p++)
        atomicAdd(&g_acc[OFF_SS + tid + p * 256], acc[p]);
}

// G = s_soft @ s_soft^T -> bf16; 128x128 tile, 256 thr, packed f32x2 FMA
__global__ void __launch_bounds__(256) k_G() {
    __shared__ float Sa[128 * 36];
    __shared__ float SbT[32 * 132];
    int tid = threadIdx.x;
    int ti = blockIdx.x >> 5, tj = blockIdx.x & 31;
    for (int i = tid; i < 1024; i += 256) {
        int row = i >> 3, q = i & 7;
        float4 va = ((const float4*)(g_s_soft + (ti * 128 + row) * 32))[q];
        *(float4*)&Sa[row * 36 + q * 4] = va;
        float4 vb = ((const float4*)(g_s_soft + (tj * 128 + row) * 32))[q];
        SbT[(q * 4 + 0) * 132 + row] = vb.x;
        SbT[(q * 4 + 1) * 132 + row] = vb.y;
        SbT[(q * 4 + 2) * 132 + row] = vb.z;
        SbT[(q * 4 + 3) * 132 + row] = vb.w;
    }
    __syncthreads();
    int ry = tid >> 4, cx = tid & 15;
    unsigned long long acc2[8][4];
#pragma unroll
    for (int i = 0; i < 8; i++)
#pragma unroll
        for (int j = 0; j < 4; j++) acc2[i][j] = 0ull;
#pragma unroll 4
    for (int k = 0; k < 32; k++) {
        unsigned long long a2[8], b2[4];
#pragma unroll
        for (int i = 0; i < 8; i++) {
            float a = Sa[(ry + 16 * i) * 36 + k];
            asm("mov.b64 %0, {%1, %1};" : "=l"(a2[i]) : "f"(a));
        }
#pragma unroll
        for (int j = 0; j < 4; j++) {
            float blo = SbT[k * 132 + cx + 32 * j];
            float bhi = SbT[k * 132 + cx + 32 * j + 16];
            asm("mov.b64 %0, {%1, %2};" : "=l"(b2[j]) : "f"(blo), "f"(bhi));
        }
#pragma unroll
        for (int i = 0; i < 8; i++)
#pragma unroll
            for (int j = 0; j < 4; j++)
                asm("fma.rn.f32x2 %0, %1, %2, %0;"
                    : "+l"(acc2[i][j]) : "l"(a2[i]), "l"(b2[j]));
    }
#pragma unroll
    for (int i = 0; i < 8; i++) {
        size_t ro = (size_t)(ti * 128 + ry + 16 * i) * NN + tj * 128 + cx;
#pragma unroll
        for (int j = 0; j < 4; j++) {
            float lo, hi;
            asm("mov.b64 {%0, %1}, %2;" : "=f"(lo), "=f"(hi) : "l"(acc2[i][j]));
            g_Gh[ro + 32 * j] = __float2bfloat16(lo);
            g_Gh[ro + 32 * j + 16] = __float2bfloat16(hi);
        }
    }
}

// grid 2048 = 256 n-tiles x 4 m-slices x 2 batch-pairs; 128 thr;
// software-pipelined: prefetch next adj/G/cluster before the bucket RMW chain.
__global__ void __launch_bounds__(128, 5) k_main(const float* __restrict__ adj) {
    __shared__ float R[2 * 32 * 128];   // 32KB, bank = tid
    int tid = threadIdx.x;
    int bp = blockIdx.x & 1, ms = (blockIdx.x >> 1) & 3, nt = blockIdx.x >> 3;
    int w = tid >> 5, r = (tid >> 3) & 3, mg = tid & 7;
    int n = nt * 16 + w * 4 + r;
    int mbase = ms * 1024;

    for (int i = tid; i < 8192; i += 128) R[i] = 0.0f;
    __syncthreads();

    float mc0 = 0, mc1 = 0, rs0 = 0, rs1 = 0;
    const uint2* Gp = (const uint2*)(g_Gh + (size_t)n * NN + mbase);
    const float4* Ap0 =
        (const float4*)(adj + ((size_t)((bp * 2 + 0) * NN + n)) * NN + mbase);
    const float4* Ap1 =
        (const float4*)(adj + ((size_t)((bp * 2 + 1) * NN + n)) * NN + mbase);
    const int4* Cp0 = (const int4*)(g_cluster + (bp * 2 + 0) * NN + mbase);
    const int4* Cp1 = (const int4*)(g_cluster + (bp * 2 + 1) * NN + mbase);

    float4 a0 = Ap0[mg], a1 = Ap1[mg];
    uint2 gg = Gp[mg];
    int4 c0 = Cp0[mg], c1 = Cp1[mg];

#pragma unroll 2
    for (int it = 0; it < 32; it++) {
        float4 na0, na1; uint2 ng; int4 nc0, nc1;
        if (it < 31) {
            int mi = (it + 1) * 8 + mg;
            na0 = Ap0[mi]; na1 = Ap1[mi];
            ng = Gp[mi];
            nc0 = Cp0[mi]; nc1 = Cp1[mi];
        }
        float2 glo = __bfloat1622float2(*(__nv_bfloat162*)&gg.x);
        float2 ghi = __bfloat1622float2(*(__nv_bfloat162*)&gg.y);
        mc0 += a0.x * glo.x + a0.y * glo.y + a0.z * ghi.x + a0.w * ghi.y;
        rs0 += (a0.x + a0.y) + (a0.z + a0.w);
        mc1 += a1.x * glo.x + a1.y * glo.y + a1.z * ghi.x + a1.w * ghi.y;
        rs1 += (a1.x + a1.y) + (a1.z + a1.w);
        float* R0 = R + tid;
        R0[c0.x << 7] += a0.x;
        R0[c0.y << 7] += a0.y;
        R0[c0.z << 7] += a0.z;
        R0[c0.w << 7] += a0.w;
        float* R1 = R + 4096 + tid;
        R1[c1.x << 7] += a1.x;
        R1[c1.y << 7] += a1.y;
        R1[c1.z << 7] += a1.z;
        R1[c1.w << 7] += a1.w;
        a0 = na0; a1 = na1; gg = ng; c0 = nc0; c1 = nc1;
    }

    const unsigned F = 0xffffffffu;
    float mcv[2] = {mc0, mc1}, rsv[2] = {rs0, rs1};
#pragma unroll
    for (int bb = 0; bb < 2; bb++) {
        int b = bp * 2 + bb;
        float v = rsv[bb];
        v += __shfl_xor_sync(F, v, 1);
        v += __shfl_xor_sync(F, v, 2);
        v += __shfl_xor_sync(F, v, 4);
        if (mg == 0) atomicAdd(&g_acc[OFF_DFLAT + b * NN + n], v);
        float m = mcv[bb];
#pragma unroll
        for (int o = 16; o > 0; o >>= 1) m += __shfl_down_sync(F, m, o);
        if ((tid & 31) == 0) atomicAdd(&g_acc[OFF_NUM + b], m);

        float vc[32];
#pragma unroll
        for (int c = 0; c < 32; c++) {
            float x = R[bb * 4096 + (c << 7) + tid];
            x += __shfl_xor_sync(F, x, 1);
            x += __shfl_xor_sync(F, x, 2);
            x += __shfl_xor_sync(F, x, 4);
            vc[c] = x;
        }
        if (mg == 0) {
            float4* dst = (float4*)(g_Rs + ((size_t)((ms * 4 + b) * NN + n)) * 32);
#pragma unroll
            for (int i = 0; i < 8; i++)
                dst[i] = make_float4(vc[4*i], vc[4*i+1], vc[4*i+2], vc[4*i+3]);
        }
    }
}

__global__ void k_emb(const float* __restrict__ emb) {
    __shared__ float acc[32 * 128];
    __shared__ int cl[64];
    int f = threadIdx.x;
    int b = blockIdx.x >> 6, ch = blockIdx.x & 63;
#pragma unroll
    for (int k = 0; k < 32; k++) acc[k * 128 + f] = 0.0f;
    if (f < 64) cl[f] = g_cluster[b * NN + ch * 64 + f];
    __syncthreads();
    float cs = 0.0f;
    int nbase = ch * 64;
    for (int r = 0; r < 64; r++) {
        float v = emb[((size_t)(b * NN + nbase + r)) * NF + f];
        cs += v;
        acc[cl[r] * 128 + f] += v;
    }
    __syncthreads();
#pragma unroll
    for (int k = 0; k < 32; k++)
        atomicAdd(&g_acc[OFF_PEMB + (b * 32 + k) * 128 + f], acc[k * 128 + f]);
    atomicAdd(&g_acc[OFF_CSUM + b * 128 + f], cs);
}

__global__ void k_oadj() {
    __shared__ float acc[8 * 32 * 32];
    __shared__ float s2[8 * 32];
    int tid = threadIdx.x, w = tid >> 5, l = tid & 31;
    int b = blockIdx.x >> 5, ch = blockIdx.x & 31;
    for (int i = tid; i < 8 * 32 * 32; i += 256) acc[i] = 0.0f;
    __syncthreads();
    float s2l = 0.0f;
    for (int r = w; r < 128; r += 8) {
        int n = ch * 128 + r;
        float as2 = EPSF * g_acc[OFF_DFLAT + b * NN + n];
#pragma unroll
        for (int s = 0; s < 4; s++)
            as2 += g_Rs[((size_t)((s * 4 + b) * NN + n)) * 32 + l];
        int c = g_cluster[b * NN + n];
        acc[(w * 32 + c) * 32 + l] += as2;
        s2l += as2;
    }
    s2[w * 32 + l] = s2l;
    __syncthreads();
#pragma unroll
    for (int p = 0; p < 4; p++) {
        int pr = tid + p * 256;
        float s = 0.0f;
#pragma unroll
        for (int ww = 0; ww < 8; ww++) s += acc[ww * 1024 + pr];
        atomicAdd(&g_acc[OFF_RAW + b * 1024 + pr], s);
    }
    if (tid < 32) {
        float s = 0.0f;
#pragma unroll
        for (int ww = 0; ww < 8; ww++) s += s2[ww * 32 + tid];
        atomicAdd(&g_acc[OFF_AS2 + b * 32 + tid], s);
    }
}

__global__ void k_fin(float* __restrict__ out) {
    __shared__ float red[256];
    __shared__ float adjb[4096];
    __shared__ float dbk[128];
    __shared__ float fro_s;
    int tid = threadIdx.x;

    float den[4] = {0, 0, 0, 0};
    for (int i = tid; i < NN; i += 256) {
        float wv = g_w[i];
#pragma unroll
        for (int b = 0; b < 4; b++) den[b] += g_acc[OFF_DFLAT + b * NN + i] * wv;
    }
    float loss = 0.0f;
    for (int b = 0; b < 4; b++) {
        red[tid] = den[b]; __syncthreads();
        for (int s = 128; s > 0; s >>= 1) {
            if (tid < s) red[tid] += red[tid + s];
            __syncthreads();
        }
        if (tid == 0) loss += g_acc[OFF_NUM + b] / red[0];
        __syncthreads();
    }
    if (tid == 0) out[OUT_MLOSS] = -0.25f * loss;

    float f2 = 0.0f;
    for (int i = tid; i < 1024; i += 256) {
        float v = g_acc[OFF_SS + i]; f2 += v * v;
    }
    red[tid] = f2; __syncthreads();
    for (int s = 128; s > 0; s >>= 1) {
        if (tid < s) red[tid] += red[tid + s];
        __syncthreads();
    }
    if (tid == 0) fro_s = sqrtf(red[0]);
    __syncthreads();
    float invf = 1.0f / fro_s;
    const float isq = 0.17677669529663687f;
    float o2 = 0.0f;
    for (int i = tid; i < 1024; i += 256) {
        float v = g_acc[OFF_SS + i] * invf;
        if ((i >> 5) == (i & 31)) v -= isq;
        o2 += v * v;
    }
    red[tid] = o2; __syncthreads();
    for (int s = 128; s > 0; s >>= 1) {
        if (tid < s) red[tid] += red[tid + s];
        __syncthreads();
    }
    if (tid == 0) out[OUT_OLOSS] = sqrtf(red[0]);

    for (int i = tid; i < 16384; i += 256) {
        int b = i >> 12, f = i & 127;
        out[OUT_EMB + i] = g_acc[OFF_PEMB + i] + EPSF * g_acc[OFF_CSUM + b * 128 + f];
    }

    for (int i = tid; i < 4096; i += 256) {
        int b = i >> 10, k = (i >> 5) & 31, l = i & 31;
        float v = (k == l) ? 0.0f
                 : g_acc[OFF_RAW + i] + EPSF * g_acc[OFF_AS2 + b * 32 + l];
        adjb[i] = v;
    }
    __syncthreads();
    if (tid < 128) {
        float s = 0.0f;
#pragma unroll
        for (int l = 0; l < 32; l++) s += adjb[tid * 32 + l];
        dbk[tid] = sqrtf(s) + EPSF;
    }
    __syncthreads();
    for (int i = tid; i < 4096; i += 256) {
        int b = i >> 10, k = (i >> 5) & 31, l = i & 31;
        out[OUT_ADJ + i] = adjb[i] / (dbk[b * 32 + k] * dbk[b * 32 + l]);
    }
}

extern "C" void kernel_launch(void* const* d_in, const int* in_sizes, int n_in,
                              void* d_out, int out_size) {
    const float* emb    = (const float*)d_in[0];
    const float* adj    = (const float*)d_in[1];
    const float* logits = (const float*)d_in[2];
    const float* gumbel = (const float*)d_in[3];
    float* out = (float*)d_out;
    k_soft<<<128, 32>>>(logits, gumbel, out);
    k_ss<<<32, 256>>>();
    k_G<<<1024, 256>>>();
    k_main<<<2048, 128>>>(adj);
    k_emb<<<256, 128>>>(emb);
    k_oadj<<<128, 256>>>();
    k_fin<<<1, 256>>>(out);
}

// round 11
// speedup vs baseline: 1.5750x; 1.0275x over previous
#include <cuda_runtime.h>
#include <cuda_bf16.h>
#include <math.h>

#define NB 4
#define NN 4096
#define NK 32
#define NF 128
#define EPSF 1e-8f

#define OFF_DFLAT 0
#define OFF_NUM   16384
#define OFF_SS    16388
#define OFF_PEMB  17412
#define OFF_CSUM  33796
#define OFF_RAW   34308
#define OFF_AS2   38404
#define ACC_TOTAL 38532

#define OUT_EMB   0
#define OUT_ADJ   16384
#define OUT_S     20480
#define OUT_MLOSS 544768
#define OUT_OLOSS 544769

__device__ float g_s_soft[NN * NK];
__device__ float g_w[NN];
__device__ int   g_cluster[NB * NN];
__device__ float g_acc[ACC_TOTAL];
__device__ float g_Rs[4u * NB * NN * NK];          // per-m-slice buckets, 8MB
__device__ __nv_bfloat16 g_Gh[(size_t)NN * NN];    // G in bf16, 32MB

__global__ void k_soft(const float* __restrict__ logits,
                       const float* __restrict__ gumbel,
                       float* __restrict__ out) {
    int n = blockIdx.x * 32 + threadIdx.x;
    for (int i = n; i < ACC_TOTAL; i += 4096) g_acc[i] = 0.0f;
    float lg[32];
    const float4* lp = (const float4*)(logits + n * NK);
#pragma unroll
    for (int i = 0; i < 8; i++) {
        float4 v = lp[i];
        lg[4*i] = v.x; lg[4*i+1] = v.y; lg[4*i+2] = v.z; lg[4*i+3] = v.w;
    }
    const float t1 = 0.99995f;
    const float t2 = 0.99995f * 0.99995f;
    float x[32], mx = -3.4e38f;
#pragma unroll
    for (int k = 0; k < 32; k++) { x[k] = lg[k] / t2; mx = fmaxf(mx, x[k]); }
    float s = 0.0f;
#pragma unroll
    for (int k = 0; k < 32; k++) { x[k] = expf(x[k] - mx); s += x[k]; }
    float inv = 1.0f / s, w = 0.0f;
#pragma unroll
    for (int k = 0; k < 32; k++) { x[k] *= inv; w += x[k] * x[k]; }
    float4* sp = (float4*)(g_s_soft + n * NK);
#pragma unroll
    for (int i = 0; i < 8; i++)
        sp[i] = make_float4(x[4*i], x[4*i+1], x[4*i+2], x[4*i+3]);
    g_w[n] = w;
#pragma unroll
    for (int b = 0; b < NB; b++) {
        const float4* gp = (const float4*)(gumbel + ((size_t)(b * NN + n)) * NK);
        float best = -3.4e38f; int bi = 0;
#pragma unroll
        for (int i = 0; i < 8; i++) {
            float4 g = gp[i];
            float z;
            z = lg[4*i+0] / t1 + g.x; if (z > best) { best = z; bi = 4*i+0; }
            z = lg[4*i+1] / t1 + g.y; if (z > best) { best = z; bi = 4*i+1; }
            z = lg[4*i+2] / t1 + g.z; if (z > best) { best = z; bi = 4*i+2; }
            z = lg[4*i+3] / t1 + g.w; if (z > best) { best = z; bi = 4*i+3; }
        }
        g_cluster[b * NN + n] = bi;
        float4* op = (float4*)(out + OUT_S + ((size_t)(b * NN + n)) * NK);
#pragma unroll
        for (int i = 0; i < 8; i++) {
            float4 o;
            o.x = (4*i+0 == bi) ? 1.0f + EPSF : EPSF;
            o.y = (4*i+1 == bi) ? 1.0f + EPSF : EPSF;
            o.z = (4*i+2 == bi) ? 1.0f + EPSF : EPSF;
            o.w = (4*i+3 == bi) ? 1.0f + EPSF : EPSF;
            op[i] = o;
        }
    }
}

// Fused: blocks [0,1024) = G gemm; [1024,1056) = ss; [1056,1312) = emb pooling.
// All depend only on k_soft, so one launch runs them concurrently.
__global__ void __launch_bounds__(256) k_fused(const float* __restrict__ emb) {
    __shared__ float S[8960];   // 35840B union
    int tid = threadIdx.x;
    int bid = blockIdx.x;

    if (bid < 1024) {
        // ---- G = s_soft @ s_soft^T -> bf16, packed column-pair stores ----
        float* Sa = S;                 // 128*36
        float* SbT = S + 4608;         // 32*132
        int ti = bid >> 5, tj = bid & 31;
        for (int i = tid; i < 1024; i += 256) {
            int row = i >> 3, q = i & 7;
            float4 va = ((const float4*)(g_s_soft + (ti * 128 + row) * 32))[q];
            *(float4*)&Sa[row * 36 + q * 4] = va;
            float4 vb = ((const float4*)(g_s_soft + (tj * 128 + row) * 32))[q];
            SbT[(q * 4 + 0) * 132 + row] = vb.x;
            SbT[(q * 4 + 1) * 132 + row] = vb.y;
            SbT[(q * 4 + 2) * 132 + row] = vb.z;
            SbT[(q * 4 + 3) * 132 + row] = vb.w;
        }
        __syncthreads();
        int ry = tid >> 4, cx = tid & 15;
        unsigned long long acc2[8][4];
#pragma unroll
        for (int i = 0; i < 8; i++)
#pragma unroll
            for (int j = 0; j < 4; j++) acc2[i][j] = 0ull;
#pragma unroll 4
        for (int k = 0; k < 32; k++) {
            unsigned long long a2[8], b2[4];
#pragma unroll
            for (int i = 0; i < 8; i++) {
                float a = Sa[(ry + 16 * i) * 36 + k];
                asm("mov.b64 %0, {%1, %1};" : "=l"(a2[i]) : "f"(a));
            }
#pragma unroll
            for (int j = 0; j < 4; j++) {
                float2 bp = *(const float2*)&SbT[k * 132 + 2 * cx + 32 * j];
                asm("mov.b64 %0, {%1, %2};" : "=l"(b2[j]) : "f"(bp.x), "f"(bp.y));
            }
#pragma unroll
            for (int i = 0; i < 8; i++)
#pragma unroll
                for (int j = 0; j < 4; j++)
                    asm("fma.rn.f32x2 %0, %1, %2, %0;"
                        : "+l"(acc2[i][j]) : "l"(a2[i]), "l"(b2[j]));
        }
#pragma unroll
        for (int i = 0; i < 8; i++) {
            size_t ro = (size_t)(ti * 128 + ry + 16 * i) * NN + tj * 128 + 2 * cx;
#pragma unroll
            for (int j = 0; j < 4; j++) {
                float lo, hi;
                asm("mov.b64 {%0, %1}, %2;" : "=f"(lo), "=f"(hi) : "l"(acc2[i][j]));
                *(__nv_bfloat162*)&g_Gh[ro + 32 * j] = __floats2bfloat162_rn(lo, hi);
            }
        }
    } else if (bid < 1056) {
        // ---- ss = s_soft^T s_soft ----
        float* tile = S;
        float acc[4] = {0, 0, 0, 0};
        int base_n = (bid - 1024) * 128;
        for (int ch = 0; ch < 4; ch++) {
            __syncthreads();
            const float4* src = (const float4*)(g_s_soft + (base_n + ch * 32) * NK);
            ((float4*)tile)[tid] = src[tid];
            __syncthreads();
#pragma unroll 4
            for (int r = 0; r < 32; r++) {
#pragma unroll
                for (int p = 0; p < 4; p++) {
                    int pr = tid + p * 256;
                    acc[p] += tile[r * 32 + (pr >> 5)] * tile[r * 32 + (pr & 31)];
                }
            }
        }
#pragma unroll
        for (int p = 0; p < 4; p++)
            atomicAdd(&g_acc[OFF_SS + tid + p * 256], acc[p]);
    } else {
        // ---- emb pooling: 256 blocks = B x 64 chunks of 64 rows ----
        float* acc = S;                          // [2][32][128]
        int* cl = (int*)(S + 8192);              // [64]
        int e = bid - 1056;
        int b = e >> 6, ch = e & 63;
        int f = tid & 127, h = tid >> 7;
        for (int i = tid; i < 8192; i += 256) acc[i] = 0.0f;
        if (tid < 64) cl[tid] = g_cluster[b * NN + ch * 64 + tid];
        __syncthreads();
        float cs = 0.0f;
        int nbase = ch * 64 + h * 32;
        float* acch = acc + h * 4096;
        for (int r = 0; r < 32; r++) {
            float v = emb[((size_t)(b * NN + nbase + r)) * NF + f];
            cs += v;
            acch[cl[h * 32 + r] * 128 + f] += v;
        }
        __syncthreads();
        if (h == 0) {
#pragma unroll
            for (int k = 0; k < 32; k++)
                atomicAdd(&g_acc[OFF_PEMB + (b * 32 + k) * 128 + f],
                          acc[k * 128 + f] + acc[4096 + k * 128 + f]);
        }
        atomicAdd(&g_acc[OFF_CSUM + b * 128 + f], cs);
    }
}

// grid 2048 = 256 n-tiles x 4 m-slices x 2 batch-pairs; 128 thr;
// depth-2 prefetch on adj/G (DRAM), depth-1 on cluster (L2-resident).
__global__ void __launch_bounds__(128, 6) k_main(const float* __restrict__ adj) {
    __shared__ float R[2 * 32 * 128];   // 32KB, bank = tid
    int tid = threadIdx.x;
    int bp = blockIdx.x & 1, ms = (blockIdx.x >> 1) & 3, nt = blockIdx.x >> 3;
    int w = tid >> 5, r = (tid >> 3) & 3, mg = tid & 7;
    int n = nt * 16 + w * 4 + r;
    int mbase = ms * 1024;

    for (int i = tid; i < 8192; i += 128) R[i] = 0.0f;
    __syncthreads();

    float mc0 = 0, mc1 = 0, rs0 = 0, rs1 = 0;
    const uint2* Gp = (const uint2*)(g_Gh + (size_t)n * NN + mbase);
    const float4* Ap0 =
        (const float4*)(adj + ((size_t)((bp * 2 + 0) * NN + n)) * NN + mbase);
    const float4* Ap1 =
        (const float4*)(adj + ((size_t)((bp * 2 + 1) * NN + n)) * NN + mbase);
    const int4* Cp0 = (const int4*)(g_cluster + (bp * 2 + 0) * NN + mbase);
    const int4* Cp1 = (const int4*)(g_cluster + (bp * 2 + 1) * NN + mbase);

    float4 a0b[2], a1b[2]; uint2 gb[2];
    a0b[0] = Ap0[mg];     a1b[0] = Ap1[mg];     gb[0] = Gp[mg];
    a0b[1] = Ap0[8 + mg]; a1b[1] = Ap1[8 + mg]; gb[1] = Gp[8 + mg];
    int4 c0 = Cp0[mg], c1 = Cp1[mg];

#pragma unroll 2
    for (int it = 0; it < 32; it++) {
        int cur = it & 1;
        float4 a0 = a0b[cur], a1 = a1b[cur];
        uint2 gg = gb[cur];
        if (it < 30) {
            int mi = (it + 2) * 8 + mg;
            a0b[cur] = Ap0[mi]; a1b[cur] = Ap1[mi]; gb[cur] = Gp[mi];
        }
        int4 nc0, nc1;
        if (it < 31) {
            int mi = (it + 1) * 8 + mg;
            nc0 = Cp0[mi]; nc1 = Cp1[mi];
        }
        float2 glo = __bfloat1622float2(*(__nv_bfloat162*)&gg.x);
        float2 ghi = __bfloat1622float2(*(__nv_bfloat162*)&gg.y);
        mc0 += a0.x * glo.x + a0.y * glo.y + a0.z * ghi.x + a0.w * ghi.y;
        rs0 += (a0.x + a0.y) + (a0.z + a0.w);
        mc1 += a1.x * glo.x + a1.y * glo.y + a1.z * ghi.x + a1.w * ghi.y;
        rs1 += (a1.x + a1.y) + (a1.z + a1.w);
        float* R0 = R + tid;
        R0[c0.x << 7] += a0.x;
        R0[c0.y << 7] += a0.y;
        R0[c0.z << 7] += a0.z;
        R0[c0.w << 7] += a0.w;
        float* R1 = R + 4096 + tid;
        R1[c1.x << 7] += a1.x;
        R1[c1.y << 7] += a1.y;
        R1[c1.z << 7] += a1.z;
        R1[c1.w << 7] += a1.w;
        c0 = nc0; c1 = nc1;
    }

    const unsigned F = 0xffffffffu;
    float mcv[2] = {mc0, mc1}, rsv[2] = {rs0, rs1};
#pragma unroll
    for (int bb = 0; bb < 2; bb++) {
        int b = bp * 2 + bb;
        float v = rsv[bb];
        v += __shfl_xor_sync(F, v, 1);
        v += __shfl_xor_sync(F, v, 2);
        v += __shfl_xor_sync(F, v, 4);
        if (mg == 0) atomicAdd(&g_acc[OFF_DFLAT + b * NN + n], v);
        float m = mcv[bb];
#pragma unroll
        for (int o = 16; o > 0; o >>= 1) m += __shfl_down_sync(F, m, o);
        if ((tid & 31) == 0) atomicAdd(&g_acc[OFF_NUM + b], m);

        float vc[32];
#pragma unroll
        for (int c = 0; c < 32; c++) {
            float x = R[bb * 4096 + (c << 7) + tid];
            x += __shfl_xor_sync(F, x, 1);
            x += __shfl_xor_sync(F, x, 2);
            x += __shfl_xor_sync(F, x, 4);
            vc[c] = x;
        }
        if (mg == 0) {
            float4* dst = (float4*)(g_Rs + ((size_t)((ms * 4 + b) * NN + n)) * 32);
#pragma unroll
            for (int i = 0; i < 8; i++)
                dst[i] = make_float4(vc[4*i], vc[4*i+1], vc[4*i+2], vc[4*i+3]);
        }
    }
}

__global__ void k_oadj() {
    __shared__ float acc[8 * 32 * 32];
    __shared__ float s2[8 * 32];
    int tid = threadIdx.x, w = tid >> 5, l = tid & 31;
    int b = blockIdx.x >> 5, ch = blockIdx.x & 31;
    for (int i = tid; i < 8 * 32 * 32; i += 256) acc[i] = 0.0f;
    __syncthreads();
    float s2l = 0.0f;
    for (int r = w; r < 128; r += 8) {
        int n = ch * 128 + r;
        float as2 = EPSF * g_acc[OFF_DFLAT + b * NN + n];
#pragma unroll
        for (int s = 0; s < 4; s++)
            as2 += g_Rs[((size_t)((s * 4 + b) * NN + n)) * 32 + l];
        int c = g_cluster[b * NN + n];
        acc[(w * 32 + c) * 32 + l] += as2;
        s2l += as2;
    }
    s2[w * 32 + l] = s2l;
    __syncthreads();
#pragma unroll
    for (int p = 0; p < 4; p++) {
        int pr = tid + p * 256;
        float s = 0.0f;
#pragma unroll
        for (int ww = 0; ww < 8; ww++) s += acc[ww * 1024 + pr];
        atomicAdd(&g_acc[OFF_RAW + b * 1024 + pr], s);
    }
    if (tid < 32) {
        float s = 0.0f;
#pragma unroll
        for (int ww = 0; ww < 8; ww++) s += s2[ww * 32 + tid];
        atomicAdd(&g_acc[OFF_AS2 + b * 32 + tid], s);
    }
}

__global__ void k_fin(float* __restrict__ out) {
    __shared__ float red[256];
    __shared__ float adjb[4096];
    __shared__ float dbk[128];
    __shared__ float fro_s;
    int tid = threadIdx.x;

    float den[4] = {0, 0, 0, 0};
    for (int i = tid; i < NN; i += 256) {
        float wv = g_w[i];
#pragma unroll
        for (int b = 0; b < 4; b++) den[b] += g_acc[OFF_DFLAT + b * NN + i] * wv;
    }
    float loss = 0.0f;
    for (int b = 0; b < 4; b++) {
        red[tid] = den[b]; __syncthreads();
        for (int s = 128; s > 0; s >>= 1) {
            if (tid < s) red[tid] += red[tid + s];
            __syncthreads();
        }
        if (tid == 0) loss += g_acc[OFF_NUM + b] / red[0];
        __syncthreads();
    }
    if (tid == 0) out[OUT_MLOSS] = -0.25f * loss;

    float f2 = 0.0f;
    for (int i = tid; i < 1024; i += 256) {
        float v = g_acc[OFF_SS + i]; f2 += v * v;
    }
    red[tid] = f2; __syncthreads();
    for (int s = 128; s > 0; s >>= 1) {
        if (tid < s) red[tid] += red[tid + s];
        __syncthreads();
    }
    if (tid == 0) fro_s = sqrtf(red[0]);
    __syncthreads();
    float invf = 1.0f / fro_s;
    const float isq = 0.17677669529663687f;
    float o2 = 0.0f;
    for (int i = tid; i < 1024; i += 256) {
        float v = g_acc[OFF_SS + i] * invf;
        if ((i >> 5) == (i & 31)) v -= isq;
        o2 += v * v;
    }
    red[tid] = o2; __syncthreads();
    for (int s = 128; s > 0; s >>= 1) {
        if (tid < s) red[tid] += red[tid + s];
        __syncthreads();
    }
    if (tid == 0) out[OUT_OLOSS] = sqrtf(red[0]);

    for (int i = tid; i < 16384; i += 256) {
        int b = i >> 12, f = i & 127;
        out[OUT_EMB + i] = g_acc[OFF_PEMB + i] + EPSF * g_acc[OFF_CSUM + b * 128 + f];
    }

    for (int i = tid; i < 4096; i += 256) {
        int b = i >> 10, k = (i >> 5) & 31, l = i & 31;
        float v = (k == l) ? 0.0f
                 : g_acc[OFF_RAW + i] + EPSF * g_acc[OFF_AS2 + b * 32 + l];
        adjb[i] = v;
    }
    __syncthreads();
    if (tid < 128) {
        float s = 0.0f;
#pragma unroll
        for (int l = 0; l < 32; l++) s += adjb[tid * 32 + l];
        dbk[tid] = sqrtf(s) + EPSF;
    }
    __syncthreads();
    for (int i = tid; i < 4096; i += 256) {
        int b = i >> 10, k = (i >> 5) & 31, l = i & 31;
        out[OUT_ADJ + i] = adjb[i] / (dbk[b * 32 + k] * dbk[b * 32 + l]);
    }
}

extern "C" void kernel_launch(void* const* d_in, const int* in_sizes, int n_in,
                              void* d_out, int out_size) {
    const float* emb    = (const float*)d_in[0];
    const float* adj    = (const float*)d_in[1];
    const float* logits = (const float*)d_in[2];
    const float* gumbel = (const float*)d_in[3];
    float* out = (float*)d_out;
    k_soft<<<128, 32>>>(logits, gumbel, out);
    k_fused<<<1312, 256>>>(emb);
    k_main<<<2048, 128>>>(adj);
    k_oadj<<<128, 256>>>();
    k_fin<<<1, 256>>>(out);
}

// round 12
// speedup vs baseline: 1.6986x; 1.0784x over previous
#include <cuda_runtime.h>
#include <cuda_bf16.h>
#include <math.h>

#define NB 4
#define NN 4096
#define NK 32
#define NF 128
#define EPSF 1e-8f

#define OFF_DFLAT 0
#define OFF_NUM   16384
#define OFF_SS    16388
#define OFF_PEMB  17412
#define OFF_CSUM  33796
#define OFF_RAW   34308
#define OFF_AS2   38404
#define ACC_TOTAL 38532

#define OUT_EMB   0
#define OUT_ADJ   16384
#define OUT_S     20480
#define OUT_MLOSS 544768
#define OUT_OLOSS 544769

__device__ float g_s_soft[NN * NK];
__device__ float g_w[NN];
__device__ int   g_cluster[NB * NN];
__device__ float g_acc[ACC_TOTAL];
__device__ float g_Rs[4u * NB * NN * NK];          // per-m-slice buckets, 8MB
__device__ __nv_bfloat16 g_Gh[(size_t)NN * NN];    // G in bf16, 32MB

__global__ void k_soft(const float* __restrict__ logits,
                       const float* __restrict__ gumbel,
                       float* __restrict__ out) {
    int n = blockIdx.x * 32 + threadIdx.x;
    for (int i = n; i < ACC_TOTAL; i += 4096) g_acc[i] = 0.0f;
    float lg[32];
    const float4* lp = (const float4*)(logits + n * NK);
#pragma unroll
    for (int i = 0; i < 8; i++) {
        float4 v = lp[i];
        lg[4*i] = v.x; lg[4*i+1] = v.y; lg[4*i+2] = v.z; lg[4*i+3] = v.w;
    }
    const float t1 = 0.99995f;
    const float t2 = 0.99995f * 0.99995f;
    float x[32], mx = -3.4e38f;
#pragma unroll
    for (int k = 0; k < 32; k++) { x[k] = lg[k] / t2; mx = fmaxf(mx, x[k]); }
    float s = 0.0f;
#pragma unroll
    for (int k = 0; k < 32; k++) { x[k] = expf(x[k] - mx); s += x[k]; }
    float inv = 1.0f / s, w = 0.0f;
#pragma unroll
    for (int k = 0; k < 32; k++) { x[k] *= inv; w += x[k] * x[k]; }
    float4* sp = (float4*)(g_s_soft + n * NK);
#pragma unroll
    for (int i = 0; i < 8; i++)
        sp[i] = make_float4(x[4*i], x[4*i+1], x[4*i+2], x[4*i+3]);
    g_w[n] = w;
#pragma unroll
    for (int b = 0; b < NB; b++) {
        const float4* gp = (const float4*)(gumbel + ((size_t)(b * NN + n)) * NK);
        float best = -3.4e38f; int bi = 0;
#pragma unroll
        for (int i = 0; i < 8; i++) {
            float4 g = gp[i];
            float z;
            z = lg[4*i+0] / t1 + g.x; if (z > best) { best = z; bi = 4*i+0; }
            z = lg[4*i+1] / t1 + g.y; if (z > best) { best = z; bi = 4*i+1; }
            z = lg[4*i+2] / t1 + g.z; if (z > best) { best = z; bi = 4*i+2; }
            z = lg[4*i+3] / t1 + g.w; if (z > best) { best = z; bi = 4*i+3; }
        }
        g_cluster[b * NN + n] = bi;
        float4* op = (float4*)(out + OUT_S + ((size_t)(b * NN + n)) * NK);
#pragma unroll
        for (int i = 0; i < 8; i++) {
            float4 o;
            o.x = (4*i+0 == bi) ? 1.0f + EPSF : EPSF;
            o.y = (4*i+1 == bi) ? 1.0f + EPSF : EPSF;
            o.z = (4*i+2 == bi) ? 1.0f + EPSF : EPSF;
            o.w = (4*i+3 == bi) ? 1.0f + EPSF : EPSF;
            op[i] = o;
        }
    }
}

// Fused: blocks [0,1024) = G gemm; [1024,1056) = ss; [1056,1312) = emb pooling.
__global__ void __launch_bounds__(256) k_fused(const float* __restrict__ emb) {
    __shared__ float S[8960];
    int tid = threadIdx.x;
    int bid = blockIdx.x;

    if (bid < 1024) {
        float* Sa = S;                 // 128*36
        float* SbT = S + 4608;         // 32*132
        int ti = bid >> 5, tj = bid & 31;
        for (int i = tid; i < 1024; i += 256) {
            int row = i >> 3, q = i & 7;
            float4 va = ((const float4*)(g_s_soft + (ti * 128 + row) * 32))[q];
            *(float4*)&Sa[row * 36 + q * 4] = va;
            float4 vb = ((const float4*)(g_s_soft + (tj * 128 + row) * 32))[q];
            SbT[(q * 4 + 0) * 132 + row] = vb.x;
            SbT[(q * 4 + 1) * 132 + row] = vb.y;
            SbT[(q * 4 + 2) * 132 + row] = vb.z;
            SbT[(q * 4 + 3) * 132 + row] = vb.w;
        }
        __syncthreads();
        int ry = tid >> 4, cx = tid & 15;
        unsigned long long acc2[8][4];
#pragma unroll
        for (int i = 0; i < 8; i++)
#pragma unroll
            for (int j = 0; j < 4; j++) acc2[i][j] = 0ull;
#pragma unroll 4
        for (int k = 0; k < 32; k++) {
            unsigned long long a2[8], b2[4];
#pragma unroll
            for (int i = 0; i < 8; i++) {
                float a = Sa[(ry + 16 * i) * 36 + k];
                asm("mov.b64 %0, {%1, %1};" : "=l"(a2[i]) : "f"(a));
            }
#pragma unroll
            for (int j = 0; j < 4; j++) {
                float2 bp = *(const float2*)&SbT[k * 132 + 2 * cx + 32 * j];
                asm("mov.b64 %0, {%1, %2};" : "=l"(b2[j]) : "f"(bp.x), "f"(bp.y));
            }
#pragma unroll
            for (int i = 0; i < 8; i++)
#pragma unroll
                for (int j = 0; j < 4; j++)
                    asm("fma.rn.f32x2 %0, %1, %2, %0;"
                        : "+l"(acc2[i][j]) : "l"(a2[i]), "l"(b2[j]));
        }
#pragma unroll
        for (int i = 0; i < 8; i++) {
            size_t ro = (size_t)(ti * 128 + ry + 16 * i) * NN + tj * 128 + 2 * cx;
#pragma unroll
            for (int j = 0; j < 4; j++) {
                float lo, hi;
                asm("mov.b64 {%0, %1}, %2;" : "=f"(lo), "=f"(hi) : "l"(acc2[i][j]));
                *(__nv_bfloat162*)&g_Gh[ro + 32 * j] = __floats2bfloat162_rn(lo, hi);
            }
        }
    } else if (bid < 1056) {
        float* tile = S;
        float acc[4] = {0, 0, 0, 0};
        int base_n = (bid - 1024) * 128;
        for (int ch = 0; ch < 4; ch++) {
            __syncthreads();
            const float4* src = (const float4*)(g_s_soft + (base_n + ch * 32) * NK);
            ((float4*)tile)[tid] = src[tid];
            __syncthreads();
#pragma unroll 4
            for (int r = 0; r < 32; r++) {
#pragma unroll
                for (int p = 0; p < 4; p++) {
                    int pr = tid + p * 256;
                    acc[p] += tile[r * 32 + (pr >> 5)] * tile[r * 32 + (pr & 31)];
                }
            }
        }
#pragma unroll
        for (int p = 0; p < 4; p++)
            atomicAdd(&g_acc[OFF_SS + tid + p * 256], acc[p]);
    } else {
        float* acc = S;                          // [2][32][128]
        int* cl = (int*)(S + 8192);              // [64]
        int e = bid - 1056;
        int b = e >> 6, ch = e & 63;
        int f = tid & 127, h = tid >> 7;
        for (int i = tid; i < 8192; i += 256) acc[i] = 0.0f;
        if (tid < 64) cl[tid] = g_cluster[b * NN + ch * 64 + tid];
        __syncthreads();
        float cs = 0.0f;
        int nbase = ch * 64 + h * 32;
        float* acch = acc + h * 4096;
        for (int r = 0; r < 32; r++) {
            float v = emb[((size_t)(b * NN + nbase + r)) * NF + f];
            cs += v;
            acch[cl[h * 32 + r] * 128 + f] += v;
        }
        __syncthreads();
        if (h == 0) {
#pragma unroll
            for (int k = 0; k < 32; k++)
                atomicAdd(&g_acc[OFF_PEMB + (b * 32 + k) * 128 + f],
                          acc[k * 128 + f] + acc[4096 + k * 128 + f]);
        }
        atomicAdd(&g_acc[OFF_CSUM + b * 128 + f], cs);
    }
}

// grid 4096 = 256 n-tiles x 4 m-slices x 4 batches (batch = low 2 bits so the
// 4 siblings share G via L2); 128 thr; depth-2 prefetch on adj/G.
__global__ void __launch_bounds__(128, 8) k_main(const float* __restrict__ adj) {
    __shared__ float R[32 * 128];   // 16KB, bank = tid
    int tid = threadIdx.x;
    int b = blockIdx.x & 3, ms = (blockIdx.x >> 2) & 3, nt = blockIdx.x >> 4;
    int w = tid >> 5, r = (tid >> 3) & 3, mg = tid & 7;
    int n = nt * 16 + w * 4 + r;
    int mbase = ms * 1024;

    for (int i = tid; i < 4096; i += 128) R[i] = 0.0f;
    __syncthreads();

    float mc = 0, rs = 0;
    const uint2* Gp = (const uint2*)(g_Gh + (size_t)n * NN + mbase);
    const float4* Ap =
        (const float4*)(adj + ((size_t)(b * NN + n)) * NN + mbase);
    const int4* Cp = (const int4*)(g_cluster + b * NN + mbase);

    float4 ab[2]; uint2 gb[2];
    ab[0] = Ap[mg];     gb[0] = Gp[mg];
    ab[1] = Ap[8 + mg]; gb[1] = Gp[8 + mg];
    int4 c = Cp[mg];

#pragma unroll 2
    for (int it = 0; it < 32; it++) {
        int cur = it & 1;
        float4 a = ab[cur];
        uint2 gg = gb[cur];
        if (it < 30) {
            int mi = (it + 2) * 8 + mg;
            ab[cur] = Ap[mi]; gb[cur] = Gp[mi];
        }
        int4 nc;
        if (it < 31) nc = Cp[(it + 1) * 8 + mg];
        float2 glo = __bfloat1622float2(*(__nv_bfloat162*)&gg.x);
        float2 ghi = __bfloat1622float2(*(__nv_bfloat162*)&gg.y);
        mc += a.x * glo.x + a.y * glo.y + a.z * ghi.x + a.w * ghi.y;
        rs += (a.x + a.y) + (a.z + a.w);
        float* R0 = R + tid;
        R0[c.x << 7] += a.x;
        R0[c.y << 7] += a.y;
        R0[c.z << 7] += a.z;
        R0[c.w << 7] += a.w;
        c = nc;
    }

    const unsigned F = 0xffffffffu;
    {
        float v = rs;
        v += __shfl_xor_sync(F, v, 1);
        v += __shfl_xor_sync(F, v, 2);
        v += __shfl_xor_sync(F, v, 4);
        if (mg == 0) atomicAdd(&g_acc[OFF_DFLAT + b * NN + n], v);
        float m = mc;
#pragma unroll
        for (int o = 16; o > 0; o >>= 1) m += __shfl_down_sync(F, m, o);
        if ((tid & 31) == 0) atomicAdd(&g_acc[OFF_NUM + b], m);

        float vc[32];
#pragma unroll
        for (int cc = 0; cc < 32; cc++) {
            float x = R[(cc << 7) + tid];
            x += __shfl_xor_sync(F, x, 1);
            x += __shfl_xor_sync(F, x, 2);
            x += __shfl_xor_sync(F, x, 4);
            vc[cc] = x;
        }
        if (mg == 0) {
            float4* dst = (float4*)(g_Rs + ((size_t)((ms * 4 + b) * NN + n)) * 32);
#pragma unroll
            for (int i = 0; i < 8; i++)
                dst[i] = make_float4(vc[4*i], vc[4*i+1], vc[4*i+2], vc[4*i+3]);
        }
    }
}

// grid 512 = B x 128 chunks of 32 rows; 256 thr = 8 warps (4 rows each)
__global__ void k_oadj() {
    __shared__ float acc[8 * 32 * 32];
    __shared__ float s2[8 * 32];
    int tid = threadIdx.x, w = tid >> 5, l = tid & 31;
    int b = blockIdx.x >> 7, ch = blockIdx.x & 127;
    for (int i = tid; i < 8 * 32 * 32; i += 256) acc[i] = 0.0f;
    __syncthreads();
    float s2l = 0.0f;
    for (int r = w; r < 32; r += 8) {
        int n = ch * 32 + r;
        float as2 = EPSF * g_acc[OFF_DFLAT + b * NN + n];
#pragma unroll
        for (int s = 0; s < 4; s++)
            as2 += g_Rs[((size_t)((s * 4 + b) * NN + n)) * 32 + l];
        int c = g_cluster[b * NN + n];
        acc[(w * 32 + c) * 32 + l] += as2;
        s2l += as2;
    }
    s2[w * 32 + l] = s2l;
    __syncthreads();
#pragma unroll
    for (int p = 0; p < 4; p++) {
        int pr = tid + p * 256;
        float s = 0.0f;
#pragma unroll
        for (int ww = 0; ww < 8; ww++) s += acc[ww * 1024 + pr];
        atomicAdd(&g_acc[OFF_RAW + b * 1024 + pr], s);
    }
    if (tid < 32) {
        float s = 0.0f;
#pragma unroll
        for (int ww = 0; ww < 8; ww++) s += s2[ww * 32 + tid];
        atomicAdd(&g_acc[OFF_AS2 + b * 32 + tid], s);
    }
}

__global__ void k_fin(float* __restrict__ out) {
    __shared__ float red[256];
    __shared__ float adjb[4096];
    __shared__ float dbk[128];
    __shared__ float fro_s;
    int tid = threadIdx.x;

    float den[4] = {0, 0, 0, 0};
    for (int i = tid; i < NN; i += 256) {
        float wv = g_w[i];
#pragma unroll
        for (int b = 0; b < 4; b++) den[b] += g_acc[OFF_DFLAT + b * NN + i] * wv;
    }
    float loss = 0.0f;
    for (int b = 0; b < 4; b++) {
        red[tid] = den[b]; __syncthreads();
        for (int s = 128; s > 0; s >>= 1) {
            if (tid < s) red[tid] += red[tid + s];
            __syncthreads();
        }
        if (tid == 0) loss += g_acc[OFF_NUM + b] / red[0];
        __syncthreads();
    }
    if (tid == 0) out[OUT_MLOSS] = -0.25f * loss;

    float f2 = 0.0f;
    for (int i = tid; i < 1024; i += 256) {
        float v = g_acc[OFF_SS + i]; f2 += v * v;
    }
    red[tid] = f2; __syncthreads();
    for (int s = 128; s > 0; s >>= 1) {
        if (tid < s) red[tid] += red[tid + s];
        __syncthreads();
    }
    if (tid == 0) fro_s = sqrtf(red[0]);
    __syncthreads();
    float invf = 1.0f / fro_s;
    const float isq = 0.17677669529663687f;
    float o2 = 0.0f;
    for (int i = tid; i < 1024; i += 256) {
        float v = g_acc[OFF_SS + i] * invf;
        if ((i >> 5) == (i & 31)) v -= isq;
        o2 += v * v;
    }
    red[tid] = o2; __syncthreads();
    for (int s = 128; s > 0; s >>= 1) {
        if (tid < s) red[tid] += red[tid + s];
        __syncthreads();
    }
    if (tid == 0) out[OUT_OLOSS] = sqrtf(red[0]);

    for (int i = tid; i < 16384; i += 256) {
        int b = i >> 12, f = i & 127;
        out[OUT_EMB + i] = g_acc[OFF_PEMB + i] + EPSF * g_acc[OFF_CSUM + b * 128 + f];
    }

    for (int i = tid; i < 4096; i += 256) {
        int b = i >> 10, k = (i >> 5) & 31, l = i & 31;
        float v = (k == l) ? 0.0f
                 : g_acc[OFF_RAW + i] + EPSF * g_acc[OFF_AS2 + b * 32 + l];
        adjb[i] = v;
    }
    __syncthreads();
    if (tid < 128) {
        float s = 0.0f;
#pragma unroll
        for (int l = 0; l < 32; l++) s += adjb[tid * 32 + l];
        dbk[tid] = sqrtf(s) + EPSF;
    }
    __syncthreads();
    for (int i = tid; i < 4096; i += 256) {
        int b = i >> 10, k = (i >> 5) & 31, l = i & 31;
        out[OUT_ADJ + i] = adjb[i] / (dbk[b * 32 + k] * dbk[b * 32 + l]);
    }
}

extern "C" void kernel_launch(void* const* d_in, const int* in_sizes, int n_in,
                              void* d_out, int out_size) {
    const float* emb    = (const float*)d_in[0];
    const float* adj    = (const float*)d_in[1];
    const float* logits = (const float*)d_in[2];
    const float* gumbel = (const float*)d_in[3];
    float* out = (float*)d_out;
    k_soft<<<128, 32>>>(logits, gumbel, out);
    k_fused<<<1312, 256>>>(emb);
    k_main<<<4096, 128>>>(adj);
    k_oadj<<<512, 256>>>();
    k_fin<<<1, 256>>>(out);
}

// round 14
// speedup vs baseline: 1.8816x; 1.1078x over previous
#include <cuda_runtime.h>
#include <cuda_bf16.h>
#include <math.h>

#define NB 4
#define NN 4096
#define NK 32
#define NF 128
#define EPSF 1e-8f

#define OFF_DFLAT 0
#define OFF_NUM   16384
#define OFF_SS    16388
#define OFF_PEMB  17412
#define OFF_CSUM  33796
#define OFF_RAW   34308
#define OFF_AS2   38404
#define ACC_TOTAL 38532

#define OUT_EMB   0
#define OUT_ADJ   16384
#define OUT_S     20480
#define OUT_MLOSS 544768
#define OUT_OLOSS 544769

__device__ float g_s_soft[NN * NK];
__device__ float g_w[NN];
__device__ int   g_cluster[NB * NN];
__device__ unsigned char g_cl8[NB * NN];
__device__ float g_acc[ACC_TOTAL];
__device__ float g_Rs[4u * NB * NN * NK];          // per-m-slice buckets, 8MB
__device__ __nv_bfloat16 g_Gh[(size_t)NN * NN];    // G in bf16, 32MB

// grid 128 x 128 threads; thread = (n, b) pair (16K threads for gumbel part)
__global__ void k_soft(const float* __restrict__ logits,
                       const float* __restrict__ gumbel,
                       float* __restrict__ out) {
    int tid = threadIdx.x;
    int gt = blockIdx.x * 128 + tid;
    for (int i = gt; i < ACC_TOTAL; i += 16384) g_acc[i] = 0.0f;
    int n = blockIdx.x * 32 + (tid >> 2);
    int b = tid & 3;
    float lg[32];
    const float4* lp = (const float4*)(logits + n * NK);
#pragma unroll
    for (int i = 0; i < 8; i++) {
        float4 v = lp[i];
        lg[4*i] = v.x; lg[4*i+1] = v.y; lg[4*i+2] = v.z; lg[4*i+3] = v.w;
    }
    const float t1 = 0.99995f;
    const float t2 = 0.99995f * 0.99995f;

    if (b == 0) {   // softmax(logits/t2) -> s_soft, w
        float x[32], mx = -3.4e38f;
#pragma unroll
        for (int k = 0; k < 32; k++) { x[k] = lg[k] / t2; mx = fmaxf(mx, x[k]); }
        float s = 0.0f;
#pragma unroll
        for (int k = 0; k < 32; k++) { x[k] = expf(x[k] - mx); s += x[k]; }
        float inv = 1.0f / s, w = 0.0f;
#pragma unroll
        for (int k = 0; k < 32; k++) { x[k] *= inv; w += x[k] * x[k]; }
        float4* sp = (float4*)(g_s_soft + n * NK);
#pragma unroll
        for (int i = 0; i < 8; i++)
            sp[i] = make_float4(x[4*i], x[4*i+1], x[4*i+2], x[4*i+3]);
        g_w[n] = w;
    }

    const float4* gp = (const float4*)(gumbel + ((size_t)(b * NN + n)) * NK);
    float best = -3.4e38f; int bi = 0;
#pragma unroll
    for (int i = 0; i < 8; i++) {
        float4 g = gp[i];
        float z;
        z = lg[4*i+0] / t1 + g.x; if (z > best) { best = z; bi = 4*i+0; }
        z = lg[4*i+1] / t1 + g.y; if (z > best) { best = z; bi = 4*i+1; }
        z = lg[4*i+2] / t1 + g.z; if (z > best) { best = z; bi = 4*i+2; }
        z = lg[4*i+3] / t1 + g.w; if (z > best) { best = z; bi = 4*i+3; }
    }
    g_cluster[b * NN + n] = bi;
    g_cl8[b * NN + n] = (unsigned char)bi;
    float4* op = (float4*)(out + OUT_S + ((size_t)(b * NN + n)) * NK);
#pragma unroll
    for (int i = 0; i < 8; i++) {
        float4 o;
        o.x = (4*i+0 == bi) ? 1.0f + EPSF : EPSF;
        o.y = (4*i+1 == bi) ? 1.0f + EPSF : EPSF;
        o.z = (4*i+2 == bi) ? 1.0f + EPSF : EPSF;
        o.w = (4*i+3 == bi) ? 1.0f + EPSF : EPSF;
        op[i] = o;
    }
}

// Fused: [0,1024) G gemm; [1024,1056) ss; [1056,1312) emb pooling.
__global__ void __launch_bounds__(256) k_fused(const float* __restrict__ emb) {
    __shared__ float S[8960];
    int tid = threadIdx.x;
    int bid = blockIdx.x;

    if (bid < 1024) {
        float* Sa = S;                 // 128*36
        float* SbT = S + 4608;         // 32*132
        int ti = bid >> 5, tj = bid & 31;
        for (int i = tid; i < 1024; i += 256) {
            int row = i >> 3, q = i & 7;
            float4 va = ((const float4*)(g_s_soft + (ti * 128 + row) * 32))[q];
            *(float4*)&Sa[row * 36 + q * 4] = va;
            float4 vb = ((const float4*)(g_s_soft + (tj * 128 + row) * 32))[q];
            SbT[(q * 4 + 0) * 132 + row] = vb.x;
            SbT[(q * 4 + 1) * 132 + row] = vb.y;
            SbT[(q * 4 + 2) * 132 + row] = vb.z;
            SbT[(q * 4 + 3) * 132 + row] = vb.w;
        }
        __syncthreads();
        int ry = tid >> 4, cx = tid & 15;
        unsigned long long acc2[8][4];
#pragma unroll
        for (int i = 0; i < 8; i++)
#pragma unroll
            for (int j = 0; j < 4; j++) acc2[i][j] = 0ull;
#pragma unroll 4
        for (int k = 0; k < 32; k++) {
            unsigned long long a2[8], b2[4];
#pragma unroll
            for (int i = 0; i < 8; i++) {
                float a = Sa[(ry + 16 * i) * 36 + k];
                asm("mov.b64 %0, {%1, %1};" : "=l"(a2[i]) : "f"(a));
            }
#pragma unroll
            for (int j = 0; j < 4; j++) {
                float2 bp = *(const float2*)&SbT[k * 132 + 2 * cx + 32 * j];
                asm("mov.b64 %0, {%1, %2};" : "=l"(b2[j]) : "f"(bp.x), "f"(bp.y));
            }
#pragma unroll
            for (int i = 0; i < 8; i++)
#pragma unroll
                for (int j = 0; j < 4; j++)
                    asm("fma.rn.f32x2 %0, %1, %2, %0;"
                        : "+l"(acc2[i][j]) : "l"(a2[i]), "l"(b2[j]));
        }
#pragma unroll
        for (int i = 0; i < 8; i++) {
            size_t ro = (size_t)(ti * 128 + ry + 16 * i) * NN + tj * 128 + 2 * cx;
#pragma unroll
            for (int j = 0; j < 4; j++) {
                float lo, hi;
                asm("mov.b64 {%0, %1}, %2;" : "=f"(lo), "=f"(hi) : "l"(acc2[i][j]));
                *(__nv_bfloat162*)&g_Gh[ro + 32 * j] = __floats2bfloat162_rn(lo, hi);
            }
        }
    } else if (bid < 1056) {
        float* tile = S;
        float acc[4] = {0, 0, 0, 0};
        int base_n = (bid - 1024) * 128;
        for (int ch = 0; ch < 4; ch++) {
            __syncthreads();
            const float4* src = (const float4*)(g_s_soft + (base_n + ch * 32) * NK);
            ((float4*)tile)[tid] = src[tid];
            __syncthreads();
#pragma unroll 4
            for (int r = 0; r < 32; r++) {
#pragma unroll
                for (int p = 0; p < 4; p++) {
                    int pr = tid + p * 256;
                    acc[p] += tile[r * 32 + (pr >> 5)] * tile[r * 32 + (pr & 31)];
                }
            }
        }
#pragma unroll
        for (int p = 0; p < 4; p++)
            atomicAdd(&g_acc[OFF_SS + tid + p * 256], acc[p]);
    } else {
        float* acc = S;                          // [2][32][128]
        int* cl = (int*)(S + 8192);              // [64]
        int e = bid - 1056;
        int b = e >> 6, ch = e & 63;
        int f = tid & 127, h = tid >> 7;
        for (int i = tid; i < 8192; i += 256) acc[i] = 0.0f;
        if (tid < 64) cl[tid] = g_cluster[b * NN + ch * 64 + tid];
        __syncthreads();
        float cs = 0.0f;
        int nbase = ch * 64 + h * 32;
        float* acch = acc + h * 4096;
        for (int r = 0; r < 32; r++) {
            float v = emb[((size_t)(b * NN + nbase + r)) * NF + f];
            cs += v;
            acch[cl[h * 32 + r] * 128 + f] += v;
        }
        __syncthreads();
        if (h == 0) {
#pragma unroll
            for (int k = 0; k < 32; k++)
                atomicAdd(&g_acc[OFF_PEMB + (b * 32 + k) * 128 + f],
                          acc[k * 128 + f] + acc[4096 + k * 128 + f]);
        }
        atomicAdd(&g_acc[OFF_CSUM + b * 128 + f], cs);
    }
}

// grid 4096 = 256 n-tiles x 4 m-slices x 4 batches; 128 thr;
// depth-4 adj prefetch, depth-2 G, byte-packed cluster ids.
__global__ void __launch_bounds__(128, 7) k_main(const float* __restrict__ adj) {
    __shared__ float R[32 * 128];   // 16KB, bank = tid
    int tid = threadIdx.x;
    int b = blockIdx.x & 3, ms = (blockIdx.x >> 2) & 3, nt = blockIdx.x >> 4;
    int w = tid >> 5, r = (tid >> 3) & 3, mg = tid & 7;
    int n = nt * 16 + w * 4 + r;
    int mbase = ms * 1024;

    for (int i = tid; i < 4096; i += 128) R[i] = 0.0f;
    __syncthreads();

    float mc = 0, rs = 0;
    const uint2* Gp = (const uint2*)(g_Gh + (size_t)n * NN + mbase);
    const float4* Ap =
        (const float4*)(adj + ((size_t)(b * NN + n)) * NN + mbase);
    const unsigned* Cp = (const unsigned*)(g_cl8 + b * NN + mbase);

    float4 ab[4]; uint2 gb[2];
#pragma unroll
    for (int i = 0; i < 4; i++) ab[i] = Ap[i * 8 + mg];
    gb[0] = Gp[mg]; gb[1] = Gp[8 + mg];
    unsigned cc = Cp[mg];

#pragma unroll 4
    for (int it = 0; it < 32; it++) {
        float4 a = ab[it & 3];
        uint2 gg = gb[it & 1];
        unsigned c = cc;
        if (it < 28) ab[it & 3] = Ap[(it + 4) * 8 + mg];
        if (it < 30) gb[it & 1] = Gp[(it + 2) * 8 + mg];
        if (it < 31) cc = Cp[(it + 1) * 8 + mg];
        float2 glo = __bfloat1622float2(*(__nv_bfloat162*)&gg.x);
        float2 ghi = __bfloat1622float2(*(__nv_bfloat162*)&gg.y);
        mc += a.x * glo.x + a.y * glo.y + a.z * ghi.x + a.w * ghi.y;
        rs += (a.x + a.y) + (a.z + a.w);
        float* R0 = R + tid;
        R0[(c & 31u) << 7] += a.x;
        R0[((c >> 8) & 31u) << 7] += a.y;
        R0[((c >> 16) & 31u) << 7] += a.z;
        R0[((c >> 24) & 31u) << 7] += a.w;
    }

    const unsigned F = 0xffffffffu;
    {
        float v = rs;
        v += __shfl_xor_sync(F, v, 1);
        v += __shfl_xor_sync(F, v, 2);
        v += __shfl_xor_sync(F, v, 4);
        if (mg == 0) atomicAdd(&g_acc[OFF_DFLAT + b * NN + n], v);
        float m = mc;
#pragma unroll
        for (int o = 16; o > 0; o >>= 1) m += __shfl_down_sync(F, m, o);
        if ((tid & 31) == 0) atomicAdd(&g_acc[OFF_NUM + b], m);

        float vc[32];
#pragma unroll
        for (int c2 = 0; c2 < 32; c2++) {
            float x = R[(c2 << 7) + tid];
            x += __shfl_xor_sync(F, x, 1);
            x += __shfl_xor_sync(F, x, 2);
            x += __shfl_xor_sync(F, x, 4);
            vc[c2] = x;
        }
        if (mg == 0) {
            float4* dst = (float4*)(g_Rs + ((size_t)((ms * 4 + b) * NN + n)) * 32);
#pragma unroll
            for (int i = 0; i < 8; i++)
                dst[i] = make_float4(vc[4*i], vc[4*i+1], vc[4*i+2], vc[4*i+3]);
        }
    }
}

// grid 512 = B x 128 chunks of 32 rows; 256 thr = 8 warps
__global__ void k_oadj() {
    __shared__ float acc[8 * 32 * 32];
    __shared__ float s2[8 * 32];
    int tid = threadIdx.x, w = tid >> 5, l = tid & 31;
    int b = blockIdx.x >> 7, ch = blockIdx.x & 127;
    for (int i = tid; i < 8 * 32 * 32; i += 256) acc[i] = 0.0f;
    __syncthreads();
    float s2l = 0.0f;
    for (int r = w; r < 32; r += 8) {
        int n = ch * 32 + r;
        float as2 = EPSF * g_acc[OFF_DFLAT + b * NN + n];
#pragma unroll
        for (int s = 0; s < 4; s++)
            as2 += g_Rs[((size_t)((s * 4 + b) * NN + n)) * 32 + l];
        int c = g_cluster[b * NN + n];
        acc[(w * 32 + c) * 32 + l] += as2;
        s2l += as2;
    }
    s2[w * 32 + l] = s2l;
    __syncthreads();
#pragma unroll
    for (int p = 0; p < 4; p++) {
        int pr = tid + p * 256;
        float s = 0.0f;
#pragma unroll
        for (int ww = 0; ww < 8; ww++) s += acc[ww * 1024 + pr];
        atomicAdd(&g_acc[OFF_RAW + b * 1024 + pr], s);
    }
    if (tid < 32) {
        float s = 0.0f;
#pragma unroll
        for (int ww = 0; ww < 8; ww++) s += s2[ww * 32 + tid];
        atomicAdd(&g_acc[OFF_AS2 + b * 32 + tid], s);
    }
}

__global__ void k_fin(float* __restrict__ out) {
    __shared__ float red[256];
    __shared__ float adjb[4096];
    __shared__ float dbk[128];
    __shared__ float fro_s;
    int tid = threadIdx.x;
    const unsigned F = 0xffffffffu;

    // mincut loss: one-pass shuffle reduction of 4 denominators
    float den[4] = {0, 0, 0, 0};
    for (int i = tid; i < NN; i += 256) {
        float wv = g_w[i];
#pragma unroll
        for (int b = 0; b < 4; b++) den[b] += g_acc[OFF_DFLAT + b * NN + i] * wv;
    }
#pragma unroll
    for (int b = 0; b < 4; b++) {
        float v = den[b];
#pragma unroll
        for (int o = 16; o > 0; o >>= 1) v += __shfl_down_sync(F, v, o);
        if ((tid & 31) == 0) red[(tid >> 5) * 4 + b] = v;
    }
    __syncthreads();
    if (tid < 32) {
        float v = red[tid];
        v += __shfl_down_sync(F, v, 16);
        v += __shfl_down_sync(F, v, 8);
        v += __shfl_down_sync(F, v, 4);
        if (tid < 4) red[64 + tid] = g_acc[OFF_NUM + tid] / v;
    }
    __syncthreads();
    if (tid == 0)
        out[OUT_MLOSS] = -0.25f * (red[64] + red[65] + red[66] + red[67]);
    __syncthreads();

    // ortho loss
    float f2 = 0.0f;
    for (int i = tid; i < 1024; i += 256) {
        float v = g_acc[OFF_SS + i]; f2 += v * v;
    }
    red[tid] = f2; __syncthreads();
    for (int s = 128; s > 0; s >>= 1) {
        if (tid < s) red[tid] += red[tid + s];
        __syncthreads();
    }
    if (tid == 0) fro_s = sqrtf(red[0]);
    __syncthreads();
    float invf = 1.0f / fro_s;
    const float isq = 0.17677669529663687f;
    float o2 = 0.0f;
    for (int i = tid; i < 1024; i += 256) {
        float v = g_acc[OFF_SS + i] * invf;
        if ((i >> 5) == (i & 31)) v -= isq;
        o2 += v * v;
    }
    red[tid] = o2; __syncthreads();
    for (int s = 128; s > 0; s >>= 1) {
        if (tid < s) red[tid] += red[tid + s];
        __syncthreads();
    }
    if (tid == 0) out[OUT_OLOSS] = sqrtf(red[0]);

    for (int i = tid; i < 16384; i += 256) {
        int b = i >> 12, f = i & 127;
        out[OUT_EMB + i] = g_acc[OFF_PEMB + i] + EPSF * g_acc[OFF_CSUM + b * 128 + f];
    }

    for (int i = tid; i < 4096; i += 256) {
        int b = i >> 10, k = (i >> 5) & 31, l = i & 31;
        float v = (k == l) ? 0.0f
                 : g_acc[OFF_RAW + i] + EPSF * g_acc[OFF_AS2 + b * 32 + l];
        adjb[i] = v;
    }
    __syncthreads();
    if (tid < 128) {
        float s = 0.0f;
#pragma unroll
        for (int l = 0; l < 32; l++) s += adjb[tid * 32 + l];
        dbk[tid] = sqrtf(s) + EPSF;
    }
    __syncthreads();
    for (int i = tid; i < 4096; i += 256) {
        int b = i >> 10, k = (i >> 5) & 31, l = i & 31;
        out[OUT_ADJ + i] = adjb[i] / (dbk[b * 32 + k] * dbk[b * 32 + l]);
    }
}

extern "C" void kernel_launch(void* const* d_in, const int* in_sizes, int n_in,
                              void* d_out, int out_size) {
    const float* emb    = (const float*)d_in[0];
    const float* adj    = (const float*)d_in[1];
    const float* logits = (const float*)d_in[2];
    const float* gumbel = (const float*)d_in[3];
    float* out = (float*)d_out;
    k_soft<<<128, 128>>>(logits, gumbel, out);
    k_fused<<<1312, 256>>>(emb);
    k_main<<<4096, 128>>>(adj);
    k_oadj<<<512, 256>>>();
    k_fin<<<1, 256>>>(out);
}